// round 11
// baseline (speedup 1.0000x reference)
#include <cuda_runtime.h>
#include <math.h>

#define NG   128
#define PN   256
#define EPG  1024
#define NN   (NG*PN)     // 32768
#define NE   (NG*EPG)    // 131072
#define DD   128
#define OUTD 10

// ---------------- device scratch ----------------
__device__ float g_h[NN*DD];
__device__ float g_nm[8*NN];              // [(r*4+c)*NN + n]
__device__ float g_aggxf[NN*64];
__device__ float g_deg[NN];
__device__ float g_aggea[NN*16];
__device__ float g_bcxf[2*NG*4*64];       // 1024 x 64:  sum_n nm * xf
__device__ float g_denr[2*NG*4];          // raw nm sums (no eps)
__device__ float g_cx[2*NG*4*DD];         // cent_x, 1024 x 128
__device__ float g_ccraw[2*NG*4*DD];      // Wgraw @ cent_x (unnormalized)
__device__ float g_hp[3*2*NG*4*DD];       // hcent partials (3 x 1024 x 128)
__device__ unsigned int g_maxbits;
__device__ unsigned int g_tix;
__device__ float g_hcw[2*NG*4*DD];
__device__ float g_Z[NN*DD];
// fused weights
__device__ float g_Wab[64*128];           // Wa@W_b2c
__device__ float g_Wasb[64*128];          // Wa@W_sb
__device__ float g_Wawbb[64*128];         // Wa@W_bb
__device__ float g_WaWbc[64*128];         // Wa@W_bc
__device__ float g_W3[16*128];            // We@W_bb
__device__ float g_biash[128];            // ba@W_b2c
__device__ float g_biasz[128];            // ba@W_sb
__device__ float g_babb[128];             // ba@W_bb
__device__ float g_baWbc[128];            // ba@W_bc
__device__ float g_Was[64*8];             // Wa@W_score
__device__ float g_bs[8];                 // ba@W_score

// ---------------- packed f32x2 helpers ----------------
typedef unsigned long long u64t;
__device__ __forceinline__ u64t pk2(float lo, float hi) {
    u64t r; asm("mov.b64 %0, {%1,%2};" : "=l"(r) : "f"(lo), "f"(hi)); return r;
}
__device__ __forceinline__ void upk2(u64t v, float& lo, float& hi) {
    asm("mov.b64 {%0,%1}, %2;" : "=f"(lo), "=f"(hi) : "l"(v));
}
__device__ __forceinline__ void fma2(u64t& d, u64t a, u64t b) {
    asm("fma.rn.f32x2 %0, %1, %2, %0;" : "+l"(d) : "l"(a), "l"(b));
}

// ---------------------------------------------------------------------------
// GEMM pass: 128 rows x 128 cols per block, 256 threads.
// ---------------------------------------------------------------------------
template<bool SC>
__device__ __forceinline__ void mma_pass2(const float* __restrict__ A, int K,
                                          const float* __restrict__ Ws,
                                          u64t* As, int row0, int tid,
                                          int tr, int tc2, u64t acc[8][4],
                                          float ascale) {
    float4 pre[2];
#pragma unroll
    for (int it = 0; it < 2; it++) {
        int idx = tid + it*256; int lr = idx >> 2, lc = (idx & 3) * 4;
        pre[it] = *(const float4*)(A + (size_t)(row0 + lr)*K + lc);
    }
    for (int k0 = 0; k0 < K; k0 += 16) {
        __syncthreads();
#pragma unroll
        for (int it = 0; it < 2; it++) {
            int idx = tid + it*256; int lr = idx >> 2, lc = (idx & 3) * 4;
            float4 v = pre[it];
            if (SC) { v.x *= ascale; v.y *= ascale; v.z *= ascale; v.w *= ascale; }
            As[lr*17 + lc + 0] = pk2(v.x, v.x);
            As[lr*17 + lc + 1] = pk2(v.y, v.y);
            As[lr*17 + lc + 2] = pk2(v.z, v.z);
            As[lr*17 + lc + 3] = pk2(v.w, v.w);
        }
        __syncthreads();
        if (k0 + 16 < K) {
#pragma unroll
            for (int it = 0; it < 2; it++) {
                int idx = tid + it*256; int lr = idx >> 2, lc = (idx & 3) * 4;
                pre[it] = *(const float4*)(A + (size_t)(row0 + lr)*K + k0 + 16 + lc);
            }
        }
#pragma unroll
        for (int kk = 0; kk < 16; kk++) {
            const float* wrow = Ws + (k0 + kk)*128;
            u64t wv[4];
#pragma unroll
            for (int jp = 0; jp < 4; jp++)
                wv[jp] = *(const u64t*)(wrow + tc2 + 32*jp);
#pragma unroll
            for (int i = 0; i < 8; i++) {
                u64t ap = As[(tr + 16*i)*17 + kk];
#pragma unroll
                for (int jp = 0; jp < 4; jp++) fma2(acc[i][jp], ap, wv[jp]);
            }
        }
    }
}

// GEMM pass with A = relu(A0 + A1 + A2), K = 128.
__device__ __forceinline__ void mma_pass_sum3(const float* __restrict__ A0,
                                              const float* __restrict__ A1,
                                              const float* __restrict__ A2,
                                              const float* __restrict__ Ws,
                                              u64t* As, int row0, int tid,
                                              int tr, int tc2, u64t acc[8][4]) {
    const int K = 128;
    for (int k0 = 0; k0 < K; k0 += 16) {
        __syncthreads();
#pragma unroll
        for (int it = 0; it < 2; it++) {
            int idx = tid + it*256; int lr = idx >> 2, lc = (idx & 3) * 4;
            size_t o = (size_t)(row0 + lr)*K + k0 + lc;
            float4 a = *(const float4*)(A0 + o);
            float4 b = *(const float4*)(A1 + o);
            float4 c = *(const float4*)(A2 + o);
            float vx = fmaxf(a.x + b.x + c.x, 0.f);
            float vy = fmaxf(a.y + b.y + c.y, 0.f);
            float vz = fmaxf(a.z + b.z + c.z, 0.f);
            float vw = fmaxf(a.w + b.w + c.w, 0.f);
            As[lr*17 + lc + 0] = pk2(vx, vx);
            As[lr*17 + lc + 1] = pk2(vy, vy);
            As[lr*17 + lc + 2] = pk2(vz, vz);
            As[lr*17 + lc + 3] = pk2(vw, vw);
        }
        __syncthreads();
#pragma unroll
        for (int kk = 0; kk < 16; kk++) {
            const float* wrow = Ws + (k0 + kk)*128;
            u64t wv[4];
#pragma unroll
            for (int jp = 0; jp < 4; jp++)
                wv[jp] = *(const u64t*)(wrow + tc2 + 32*jp);
#pragma unroll
            for (int i = 0; i < 8; i++) {
                u64t ap = As[(tr + 16*i)*17 + kk];
#pragma unroll
                for (int jp = 0; jp < 4; jp++) fma2(acc[i][jp], ap, wv[jp]);
            }
        }
    }
}

__device__ __forceinline__ void acc_store(u64t acc[8][4], float* __restrict__ out,
                                          int row0, int tr, int tc2, int relu_flag) {
#pragma unroll
    for (int i = 0; i < 8; i++) {
        int row = row0 + tr + 16*i;
#pragma unroll
        for (int jp = 0; jp < 4; jp++) {
            int cb = tc2 + 32*jp;
            float lo, hi; upk2(acc[i][jp], lo, hi);
            if (relu_flag) { lo = fmaxf(lo, 0.f); hi = fmaxf(hi, 0.f); }
            out[(size_t)row*128 + cb]     = lo;
            out[(size_t)row*128 + cb + 1] = hi;
        }
    }
}

__device__ __forceinline__ void gemm_body(
        const float* __restrict__ A1, const float* __restrict__ W1, int K1,
        const float* __restrict__ A2, const float* __restrict__ W2, int K2,
        const float* __restrict__ A3, const float* __restrict__ W3, int K3,
        const float* __restrict__ bias,
        const float* __restrict__ rowscale,
        const float* __restrict__ rowvec,
        int relu_flag, float* __restrict__ out,
        int blk, float* sm) {
    float* Ws1 = sm;
    float* Ws2 = Ws1 + K1*128;
    float* Ws3 = Ws2 + K2*128;
    u64t*  As  = (u64t*)(Ws3 + K3*128);

    const int tid = threadIdx.x;
    const int tr = tid >> 4, tc2 = (tid & 15) * 2;
    const int row0 = blk * 128;

    for (int i = tid*4; i < K1*128; i += 1024) *(float4*)(Ws1+i) = *(const float4*)(W1+i);
    if (A2) for (int i = tid*4; i < K2*128; i += 1024) *(float4*)(Ws2+i) = *(const float4*)(W2+i);
    if (A3) for (int i = tid*4; i < K3*128; i += 1024) *(float4*)(Ws3+i) = *(const float4*)(W3+i);

    u64t acc[8][4];
#pragma unroll
    for (int i = 0; i < 8; i++)
#pragma unroll
        for (int j = 0; j < 4; j++) acc[i][j] = 0ull;

    mma_pass2<false>(A1, K1, Ws1, As, row0, tid, tr, tc2, acc, 1.f);
    if (A2) mma_pass2<false>(A2, K2, Ws2, As, row0, tid, tr, tc2, acc, 1.f);
    if (A3) mma_pass2<false>(A3, K3, Ws3, As, row0, tid, tr, tc2, acc, 1.f);

#pragma unroll
    for (int i = 0; i < 8; i++) {
        int row = row0 + tr + 16*i;
        float rs = rowscale ? rowscale[row] : 0.f;
#pragma unroll
        for (int jp = 0; jp < 4; jp++) {
            int cb = tc2 + 32*jp;
            float lo, hi; upk2(acc[i][jp], lo, hi);
            if (bias)   { lo += bias[cb];        hi += bias[cb+1]; }
            if (rowvec) { lo += rs * rowvec[cb]; hi += rs * rowvec[cb+1]; }
            if (relu_flag) { lo = fmaxf(lo, 0.f); hi = fmaxf(hi, 0.f); }
            out[(size_t)row*128 + cb]     = lo;
            out[(size_t)row*128 + cb + 1] = hi;
        }
    }
}

// ---------------------------------------------------------------------------
// nm body: scores = xf@Was + bs, softmax over centroids. 64 nodes, 256 thr.
// ---------------------------------------------------------------------------
__device__ __forceinline__ void nm_body(const float* __restrict__ xf, int n0,
                                        float* sm) {
    float* xs  = sm;            // 64*65
    float* ss  = xs + 64*65;    // 512
    float* Ws  = ss + 512;      // 512
    float* bss = Ws + 512;      // 8
    int tid = threadIdx.x;

    for (int i = tid; i < 64*64; i += 256) {
        int rw = i >> 6, k = i & 63;
        xs[rw*65 + k] = xf[(size_t)(n0 + rw)*64 + k];
    }
    for (int i = tid; i < 64*8; i += 256) Ws[i] = g_Was[i];
    if (tid < 8) bss[tid] = g_bs[tid];
    __syncthreads();

    int node = tid >> 2, q = tid & 3;
    float s0 = bss[q], s1 = bss[q + 4];
    for (int k = 0; k < 64; k++) {
        float a = xs[node*65 + k];
        s0 = fmaf(a, Ws[k*8 + q], s0);
        s1 = fmaf(a, Ws[k*8 + q + 4], s1);
    }
    ss[node*8 + q]     = s0;
    ss[node*8 + q + 4] = s1;
    __syncthreads();

    if (tid < 128) {
        int nd = tid >> 1, r = tid & 1;
        float v[4];
#pragma unroll
        for (int c = 0; c < 4; c++) v[c] = ss[nd*8 + c*2 + r];
        float m = fmaxf(fmaxf(v[0], v[1]), fmaxf(v[2], v[3]));
        float e[4], sum = 0.f;
#pragma unroll
        for (int c = 0; c < 4; c++) { e[c] = expf(v[c] - m); sum += e[c]; }
        float inv = 1.f / sum;
        int n = n0 + nd;
#pragma unroll
        for (int c = 0; c < 4; c++)
            g_nm[(size_t)(r*4 + c)*NN + n] = e[c] * inv;
    }
}

// ---------------------------------------------------------------------------
// MEGA1: blocks 0-255 h-GEMM, 256-767 nm.
// ---------------------------------------------------------------------------
__global__ void __launch_bounds__(256, 2)
mega1(const float* __restrict__ x_feat) {
    extern __shared__ float sm[];
    int b = blockIdx.x;
    if (b < 256) {
        gemm_body(x_feat, g_Wab, 64, nullptr, nullptr, 0, nullptr, nullptr, 0,
                  g_biash, nullptr, nullptr, 1, g_h, b, sm);
    } else {
        nm_body(x_feat, (b - 256) * 64, sm);
    }
}

// ---------------------------------------------------------------------------
// MEGA2: blocks 0-255 Z-GEMM (K=144);
// blocks 256-279: hcent partial GEMMs (hb = t&7, p = t>>3):
//   p0: bcxf(K=64)@WaWbc + denr*baWbc ; p1: (ccraw/max)@Wcc ; p2: cx@Wsc.
// The LAST 8 hp blocks to finish (tickets 16..23) spin until all 24 partials
// are stored, then compute hcw tiles: hcw = relu(hp0+hp1+hp2)@Wcb.
// ---------------------------------------------------------------------------
__global__ void __launch_bounds__(256, 2)
mega2(const float* __restrict__ x_feat,
      const float* __restrict__ Wcc_, const float* __restrict__ Wsc,
      const float* __restrict__ Wcb) {
    extern __shared__ float sm[];
    __shared__ int tick_s;
    int b = blockIdx.x;
    if (b < 256) {
        gemm_body(g_aggxf, g_Wawbb, 64, x_feat, g_Wasb, 64, g_aggea, g_W3, 16,
                  g_biasz, g_deg, g_babb, 0, g_Z, b, sm);
        return;
    }
    const int t = b - 256;                 // 0..23
    const int hb = t & 7, p = t >> 3;
    const int tid = threadIdx.x;
    const int tr = tid >> 4, tc2 = (tid & 15) * 2;

    if (p == 0) {
        gemm_body(g_bcxf, g_WaWbc, 64, nullptr, nullptr, 0, nullptr, nullptr, 0,
                  nullptr, g_denr, g_baWbc, 0, g_hp, hb, sm);
    } else {
        float* Ws = sm;
        u64t*  As = (u64t*)(sm + 128*128);
        const int row0 = hb * 128;
        const float* Wsel = (p == 1) ? Wcc_ : Wsc;
        const float* Asel = (p == 1) ? g_ccraw : g_cx;
        const float ascale = (p == 1)
            ? 1.f / (__uint_as_float(g_maxbits) + 1e-9f) : 1.f;
        for (int i = tid*4; i < 128*128; i += 1024)
            *(float4*)(Ws+i) = *(const float4*)(Wsel+i);
        u64t acc[8][4];
#pragma unroll
        for (int i = 0; i < 8; i++)
#pragma unroll
            for (int j = 0; j < 4; j++) acc[i][j] = 0ull;
        mma_pass2<true>(Asel, 128, Ws, As, row0, tid, tr, tc2, acc, ascale);
        acc_store(acc, g_hp + (size_t)p*131072, row0, tr, tc2, 0);
    }

    // ticket: last 8 arrivals compute hcw tiles
    __threadfence();
    __syncthreads();
    if (tid == 0) tick_s = (int)atomicAdd(&g_tix, 1u);
    __syncthreads();
    int ticket = tick_s;
    if (ticket >= 16) {
        if (tid == 0) { while (atomicAdd(&g_tix, 0u) < 24u) {} }
        __syncthreads();
        const int hb2 = ticket - 16;
        float* Ws = sm;
        u64t*  As = (u64t*)(sm + 128*128);
        for (int i = tid*4; i < 128*128; i += 1024)
            *(float4*)(Ws+i) = *(const float4*)(Wcb+i);
        u64t acc[8][4];
#pragma unroll
        for (int i = 0; i < 8; i++)
#pragma unroll
            for (int j = 0; j < 4; j++) acc[i][j] = 0ull;
        mma_pass_sum3(g_hp, g_hp + 131072, g_hp + 262144,
                      Ws, As, hb2*128, tid, tr, tc2, acc);
        acc_store(acc, g_hcw, hb2*128, tr, tc2, 0);
    }
}

// ---------------------------------------------------------------------------
// Parallel weight precompute + counters reset.  grid = 277 x 128.
// ---------------------------------------------------------------------------
__global__ void prep_big(const float* __restrict__ Wa, const float* __restrict__ ba,
                         const float* __restrict__ Wb2c, const float* __restrict__ Wsb,
                         const float* __restrict__ Wbb, const float* __restrict__ We,
                         const float* __restrict__ Wbc, const float* __restrict__ Wscore) {
    int b = blockIdx.x, d = threadIdx.x;
    if (b < 64) {
        float a = 0.f;
        for (int k = 0; k < 128; k++) a = fmaf(Wa[b*128+k], Wb2c[k*128+d], a);
        g_Wab[b*128+d] = a;
    } else if (b < 128) {
        int f = b - 64; float a = 0.f;
        for (int k = 0; k < 128; k++) a = fmaf(Wa[f*128+k], Wsb[k*128+d], a);
        g_Wasb[f*128+d] = a;
    } else if (b < 144) {
        int q = b - 128; float a = 0.f;
        for (int k = 0; k < 128; k++) a = fmaf(We[q*128+k], Wbb[k*128+d], a);
        g_W3[q*128+d] = a;
    } else if (b < 208) {
        int f = b - 144; float a = 0.f;
        for (int k = 0; k < 128; k++) a = fmaf(Wa[f*128+k], Wbb[k*128+d], a);
        g_Wawbb[f*128+d] = a;
    } else if (b < 272) {
        int f = b - 208; float a = 0.f;
        for (int k = 0; k < 128; k++) a = fmaf(Wa[f*128+k], Wbc[k*128+d], a);
        g_WaWbc[f*128+d] = a;
    } else if (b == 272) {
        float a = 0.f;
        for (int k = 0; k < 128; k++) a = fmaf(ba[k], Wb2c[k*128+d], a);
        g_biash[d] = a;
    } else if (b == 273) {
        float a = 0.f;
        for (int k = 0; k < 128; k++) a = fmaf(ba[k], Wsb[k*128+d], a);
        g_biasz[d] = a;
    } else if (b == 274) {
        float a = 0.f;
        for (int k = 0; k < 128; k++) a = fmaf(ba[k], Wbb[k*128+d], a);
        g_babb[d] = a;
        if (d == 0) { g_maxbits = 0u; g_tix = 0u; }
    } else if (b == 275) {
        float a = 0.f;
        for (int k = 0; k < 128; k++) a = fmaf(ba[k], Wbc[k*128+d], a);
        g_baWbc[d] = a;
    } else {
        for (int o = d; o < 520; o += 128) {
            int r = o >> 3, q = o & 7;
            const float* L = (r < 64) ? (Wa + r*128) : ba;
            float a = 0.f;
            for (int k = 0; k < 128; k++) a = fmaf(L[k], Wscore[k*8+q], a);
            if (r < 64) g_Was[r*8+q] = a; else g_bs[q] = a;
        }
    }
}

// ---------------------------------------------------------------------------
// Per-graph fused kernel.  1 block / graph, 1024 threads, one edge / thread.
// Computes aggea/aggxf/deg, numh/denr, bcxf, cent_x, ccraw in-block.
// ---------------------------------------------------------------------------
__global__ void __launch_bounds__(1024)
graph_kernel(const float* __restrict__ xf,
             const float* __restrict__ edge_attr,
             const int* __restrict__ ei,
             const float* __restrict__ Wedge) {
    extern __shared__ float smf[];
    float* nm_sm    = smf;               // 2048
    float* srcw     = nm_sm + 2048;      // 2048
    float* ea_sm    = srcw + 2048;       // 16384  (reused later as cx_sm)
    float* wnum_c   = ea_sm + 16384;     // 8192   (reused later as We_sm)
    float* numh_sm  = wnum_c + 8192;     // 1024
    float* bcxf_sm  = numh_sm + 1024;    // 512
    float* red_sm   = bcxf_sm + 512;     // 1024
    float* numea_sm = red_sm + 1024;     // 128
    float* w_sm     = numea_sm + 128;    // 24
    float* den_sm   = w_sm + 24;         // 8
    float* denr_sm  = den_sm + 8;        // 8
    int* sl  = (int*)(denr_sm + 8);      // 1024
    int* dl  = sl + 1024;                // 1024
    int* deg = dl + 1024;                // 256
    int* off = deg + 256;                // 257
    int* cur = off + 257;                // 256
    int* csr = cur + 256;                // 1024

    float* cx_sm = ea_sm;                // alias (free by cx phase)
    float* We_sm = wnum_c;               // alias (free by cx phase)

    const int g = blockIdx.x;
    const int tid = threadIdx.x;
    const int gb = g * PN;
    const int ge = g * EPG;

    if (tid < PN) deg[tid] = 0;
    if (tid < 20) w_sm[tid] = 0.f;
    if (tid < 512) bcxf_sm[tid] = 0.f;
    for (int i = tid; i < 2048; i += 1024) {
        srcw[i] = 0.f;
        nm_sm[i] = g_nm[(size_t)(i >> 8)*NN + gb + (i & 255)];
    }
    __syncthreads();

    // ---- edge pass: one edge per thread ----
    float wp[20];
    {
        const int e = tid;
        int s = ei[ge + e] - gb;
        int d = ei[NE + ge + e] - gb;
        sl[e] = s; dl[e] = d;
        atomicAdd(&deg[d], 1);
        const float4* earow = (const float4*)(edge_attr + (size_t)(ge + e)*16);
        float4* eadst = (float4*)(ea_sm + e*16);
        eadst[0] = earow[0]; eadst[1] = earow[1];
        eadst[2] = earow[2]; eadst[3] = earow[3];

        float ns[8], nd[8];
#pragma unroll
        for (int rc = 0; rc < 8; rc++) {
            ns[rc] = nm_sm[rc*256 + s];
            nd[rc] = nm_sm[rc*256 + d];
            float wv = nd[rc]*nd[rc]*ns[rc];
            wnum_c[e*8 + rc] = wv;
            atomicAdd(&srcw[rc*256 + s], wv);
        }
#pragma unroll
        for (int r = 0; r < 2; r++) {
            int b = r*4, w0 = r*10;
            wp[w0+0] = ns[b+0]*nd[b+1];
            wp[w0+1] = ns[b+0]*nd[b+2];
            wp[w0+2] = ns[b+0]*nd[b+3];
            wp[w0+3] = ns[b+1]*nd[b+2];
            wp[w0+4] = ns[b+1]*nd[b+3];
            wp[w0+5] = ns[b+2]*nd[b+3];
#pragma unroll
            for (int c = 0; c < 4; c++) wp[w0+6+c] = ns[b+c]*nd[b+c];
        }
    }
#pragma unroll
    for (int p = 0; p < 20; p++)
        for (int o = 16; o > 0; o >>= 1)
            wp[p] += __shfl_down_sync(0xffffffffu, wp[p], o);
    if ((tid & 31) == 0)
#pragma unroll
        for (int p = 0; p < 20; p++) atomicAdd(&w_sm[p], wp[p]);
    __syncthreads();

    // ---- numea partials ----
    {
        const int eh = tid >> 7, rcb = (tid >> 4) & 7, qb = tid & 15;
        float nacc = 0.f;
        for (int el = eh*128; el < eh*128 + 128; el++)
            nacc = fmaf(wnum_c[el*8 + rcb], ea_sm[el*16 + qb], nacc);
        red_sm[tid] = nacc;
    }
    __syncthreads();
    if (tid < 256) {
        int rc = tid >> 5, lane = tid & 31;
        float s = 0.f;
        for (int n = lane; n < PN; n += 32) s += nm_sm[rc*256 + n];
        for (int o = 16; o > 0; o >>= 1) s += __shfl_down_sync(0xffffffffu, s, o);
        if (lane == 0) { denr_sm[rc] = s; den_sm[rc] = s + 1e-6f; }
    }
    if (tid >= 512 && tid < 640) {
        int t = tid - 512;
        float v = 0.f;
#pragma unroll
        for (int j = 0; j < 8; j++) v += red_sm[t + j*128];
        numea_sm[t] = v;
    }

    // ---- CSR scan (warp 0) ----
    if (tid < 32) {
        int run = 0;
        for (int seg = 0; seg < 8; seg++) {
            int dv = deg[seg*32 + tid];
            int v = dv;
#pragma unroll
            for (int o = 1; o < 32; o <<= 1) {
                int t = __shfl_up_sync(0xffffffffu, v, o);
                if ((tid & 31) >= o) v += t;
            }
            off[seg*32 + tid] = run + v - dv;
            run += __shfl_sync(0xffffffffu, v, 31);
        }
        if (tid == 31) off[PN] = run;
    }
    __syncthreads();
    if (tid < PN) cur[tid] = off[tid];
    __syncthreads();
    {
        int pos = atomicAdd(&cur[dl[tid]], 1);
        csr[pos] = tid;
    }
    __syncthreads();

    if (tid < PN) g_deg[gb + tid] = (float)deg[tid];

    for (int i = tid; i < PN*16; i += 1024) {
        int nl = i >> 4, q = i & 15;
        float a = 0.f;
        int e0 = off[nl], e1 = off[nl + 1];
        for (int ii = e0; ii < e1; ii++)
            a += ea_sm[csr[ii]*16 + q];
        g_aggea[(size_t)(gb + nl)*16 + q] = a;
    }

    // aggxf (CSR gather) + bcxf (nm-weighted xf sums), thread = (grp16, d64)
    {
        const int d64 = tid & 63, grp = tid >> 6;
        float bl[8];
#pragma unroll
        for (int rc = 0; rc < 8; rc++) bl[rc] = 0.f;
        for (int nl = grp; nl < PN; nl += 16) {
            float xv = xf[(size_t)(gb + nl)*64 + d64];
#pragma unroll
            for (int rc = 0; rc < 8; rc++)
                bl[rc] = fmaf(nm_sm[rc*256 + nl], xv, bl[rc]);
            float a = 0.f;
            int e0 = off[nl], e1 = off[nl + 1];
            for (int ii = e0; ii < e1; ii++)
                a += xf[(size_t)(gb + sl[csr[ii]])*64 + d64];
            g_aggxf[(size_t)(gb + nl)*64 + d64] = a;
        }
#pragma unroll
        for (int rc = 0; rc < 8; rc++)
            atomicAdd(&bcxf_sm[rc*64 + d64], bl[rc]);
    }

    // ---- vector phase: numh only ----
    const int d = tid & 127, grp8 = tid >> 7;
    float numa[8];
#pragma unroll
    for (int rc = 0; rc < 8; rc++) numa[rc] = 0.f;

    for (int nl = grp8; nl < PN; nl += 8) {
        float hv = g_h[(size_t)(gb + nl)*128 + d];
#pragma unroll
        for (int rc = 0; rc < 8; rc++)
            numa[rc] = fmaf(nm_sm[rc*256 + nl] + srcw[rc*256 + nl], hv, numa[rc]);
    }
    __syncthreads();
    for (int gg = 0; gg < 8; gg++) {
        if (grp8 == gg) {
            if (gg == 0)
#pragma unroll
                for (int rc = 0; rc < 8; rc++) numh_sm[rc*128 + d] = numa[rc];
            else
#pragma unroll
                for (int rc = 0; rc < 8; rc++) numh_sm[rc*128 + d] += numa[rc];
        }
        __syncthreads();
    }

    // write bcxf + denr
    if (tid < 512) {
        int rc = tid >> 6, q = tid & 63;
        int r = rc >> 2, ci = rc & 3;
        g_bcxf[((size_t)(r*NG + g)*4 + ci)*64 + q] = bcxf_sm[tid];
    }
    if (tid < 8) {
        int r = tid >> 2, ci = tid & 3;
        g_denr[(size_t)(r*NG + g)*4 + ci] = denr_sm[tid];
    }

    // ---- cx / ccraw phase (1024 threads = 8 rc x 128 d) ----
    {
        const int rc = tid >> 7, dd = tid & 127;
        const int r = rc >> 2, ci = rc & 3;
        for (int i = tid; i < 2048; i += 1024) We_sm[i] = Wedge[i];
        __syncthreads();
        float v = numh_sm[rc*128 + dd];
#pragma unroll
        for (int q = 0; q < 16; q++)
            v = fmaf(numea_sm[rc*16 + q], We_sm[q*128 + dd], v);
        v /= den_sm[rc];
        cx_sm[rc*128 + dd] = v;
        g_cx[((size_t)(r*NG + g)*4 + ci)*128 + dd] = v;
        __syncthreads();
        const int pidx[4][4] = { {6,0,1,2}, {0,7,3,4}, {1,3,8,5}, {2,4,5,9} };
        float a = 0.f;
#pragma unroll
        for (int j = 0; j < 4; j++) {
            float w = w_sm[r*10 + pidx[ci][j]];
            if (ci == j) w *= 0.5f;
            a = fmaf(w, cx_sm[(r*4 + j)*128 + dd], a);
        }
        g_ccraw[((size_t)(r*NG + g)*4 + ci)*128 + dd] = a;
    }

    if (tid < 32) {
        const int pidx[4][4] = { {6,0,1,2}, {0,7,3,4}, {1,3,8,5}, {2,4,5,9} };
        int r = tid >> 4, idx = tid & 15;
        int i = idx >> 2, j = idx & 3;
        float v = w_sm[r*10 + pidx[i][j]];
        if (i == j) v *= 0.5f;
        float m = v;
        for (int o = 16; o > 0; o >>= 1)
            m = fmaxf(m, __shfl_down_sync(0xffffffffu, m, o));
        if (tid == 0) atomicMax(&g_maxbits, __float_as_uint(m));
    }
}

// ---------------------------------------------------------------------------
// Final fused: node = mean_r relu(Z + Sum_c nm*hcw); pool; heads.  grid = NG
// ---------------------------------------------------------------------------
__global__ void __launch_bounds__(1024)
final_kernel(const float* __restrict__ W_inter,
             const float* __restrict__ b_inter,
             const float* __restrict__ W_out,
             const float* __restrict__ b_out,
             float* __restrict__ out) {
    __shared__ float hcw[1024], nm_s[2048], red[1024], gs[128], emb[128];
    int g = blockIdx.x, tid = threadIdx.x;
    {
        int r = tid >> 9;
        hcw[tid] = g_hcw[(size_t)(r*NG + g)*512 + (tid & 511)];
    }
    for (int i = tid; i < 2048; i += 1024)
        nm_s[i] = g_nm[(size_t)(i >> 8)*NN + g*PN + (i & 255)];
    __syncthreads();

    int d = tid & 127, q8 = tid >> 7;
    float acc = 0.f;
    for (int nl = q8; nl < PN; nl += 8) {
        float z = g_Z[(size_t)(g*PN + nl)*128 + d];
        float y0 = 0.f, y1 = 0.f;
#pragma unroll
        for (int c = 0; c < 4; c++) {
            y0 = fmaf(nm_s[c*256 + nl],       hcw[c*128 + d],       y0);
            y1 = fmaf(nm_s[(4 + c)*256 + nl], hcw[512 + c*128 + d], y1);
        }
        acc += 0.5f * (fmaxf(z + y0, 0.f) + fmaxf(z + y1, 0.f));
    }
    red[tid] = acc;
    __syncthreads();
    if (tid < 128) {
        float s = 0.f;
#pragma unroll
        for (int j = 0; j < 8; j++) s += red[tid + j*128];
        gs[tid] = s * (1.0f / PN);
    }
    __syncthreads();
    if (tid < 128) {
        float e = b_inter[tid];
        for (int k = 0; k < 128; k++) e = fmaf(gs[k], W_inter[k*128 + tid], e);
        emb[tid] = e;
    }
    __syncthreads();
    if (tid < OUTD) {
        float o = b_out[tid];
        for (int k = 0; k < 128; k++) o = fmaf(emb[k], W_out[k*OUTD + tid], o);
        out[g*OUTD + tid] = o;
    }
}

// ---------------------------------------------------------------------------
extern "C" void kernel_launch(void* const* d_in, const int* in_sizes, int n_in,
                              void* d_out, int out_size) {
    const float* x_feat    = (const float*)d_in[0];
    const float* edge_attr = (const float*)d_in[1];
    const float* W_atom    = (const float*)d_in[2];
    const float* b_atom    = (const float*)d_in[3];
    const float* W_score   = (const float*)d_in[4];
    const float* W_edge    = (const float*)d_in[5];
    const float* W_b2c     = (const float*)d_in[6];
    const float* W_bb      = (const float*)d_in[7];
    const float* W_bc      = (const float*)d_in[8];
    const float* W_cb      = (const float*)d_in[9];
    const float* W_cc      = (const float*)d_in[10];
    const float* W_sb      = (const float*)d_in[11];
    const float* W_sc      = (const float*)d_in[12];
    const float* W_inter   = (const float*)d_in[13];
    const float* b_inter   = (const float*)d_in[14];
    const float* W_out     = (const float*)d_in[15];
    const float* b_out     = (const float*)d_in[16];
    const int*   edge_index= (const int*)d_in[17];
    float* out = (float*)d_out;

    cudaFuncSetAttribute(mega1, cudaFuncAttributeMaxDynamicSharedMemorySize, 52000);
    cudaFuncSetAttribute(mega2, cudaFuncAttributeMaxDynamicSharedMemorySize, 95000);
    cudaFuncSetAttribute(graph_kernel, cudaFuncAttributeMaxDynamicSharedMemorySize, 145000);

    const size_t smA = 128*17*8;   // packed u64 A tile = 17408

    // 1. fused weights + counter reset
    prep_big<<<277, 128>>>(W_atom, b_atom, W_b2c, W_sb, W_bb, W_edge, W_bc, W_score);
    // 2. h-GEMM + nm in one launch
    mega1<<<768, 256, 64*512 + smA>>>(x_feat);
    // 3. per-graph fused pass (aggea/aggxf/deg, numh, bcxf, cx, ccraw)
    graph_kernel<<<NG, 1024, 141000>>>(x_feat, edge_attr, edge_index, W_edge);
    // 4. Z-GEMM + hcent partials + in-kernel hcw (ticket barrier), one wave
    mega2<<<280, 256, (64+64+16)*512 + smA>>>(x_feat, W_cc, W_sc, W_cb);
    // 5. fused Y + relu + mean + pool + heads
    final_kernel<<<NG, 1024>>>(W_inter, b_inter, W_out, b_out, out);
}

// round 12
// speedup vs baseline: 1.6596x; 1.6596x over previous
#include <cuda_runtime.h>
#include <math.h>

#define NG   128
#define PN   256
#define EPG  1024
#define NN   (NG*PN)     // 32768
#define NE   (NG*EPG)    // 131072
#define DD   128
#define OUTD 10

// ---------------- device scratch ----------------
__device__ float g_h[NN*DD];
__device__ float g_nm[8*NN];              // [(r*4+c)*NN + n]
__device__ float g_aggxf[NN*64];
__device__ float g_deg[NN];
__device__ float g_aggea[NN*16];
__device__ float g_bcxf[2*NG*4*64];       // 1024 x 64:  sum_n nm * xf
__device__ float g_denr[2*NG*4];          // raw nm sums (no eps)
__device__ float g_cx[2*NG*4*DD];         // cent_x, 1024 x 128
__device__ float g_ccraw[2*NG*4*DD];      // Wgraw @ cent_x (unnormalized)
__device__ float g_hp[3*2*NG*4*DD];       // hcent partials (3 x 1024 x 128)
__device__ unsigned int g_maxbits;
__device__ float g_Z[NN*DD];
// fused weights
__device__ float g_Wab[64*128];           // Wa@W_b2c
__device__ float g_Wasb[64*128];          // Wa@W_sb
__device__ float g_Wawbb[64*128];         // Wa@W_bb
__device__ float g_WaWbc[64*128];         // Wa@W_bc
__device__ float g_W3[16*128];            // We@W_bb
__device__ float g_biash[128];            // ba@W_b2c
__device__ float g_biasz[128];            // ba@W_sb
__device__ float g_babb[128];             // ba@W_bb
__device__ float g_baWbc[128];            // ba@W_bc
__device__ float g_Was[64*8];             // Wa@W_score
__device__ float g_bs[8];                 // ba@W_score

// ---------------- packed f32x2 helpers ----------------
typedef unsigned long long u64t;
__device__ __forceinline__ u64t pk2(float lo, float hi) {
    u64t r; asm("mov.b64 %0, {%1,%2};" : "=l"(r) : "f"(lo), "f"(hi)); return r;
}
__device__ __forceinline__ void upk2(u64t v, float& lo, float& hi) {
    asm("mov.b64 {%0,%1}, %2;" : "=f"(lo), "=f"(hi) : "l"(v));
}
__device__ __forceinline__ void fma2(u64t& d, u64t a, u64t b) {
    asm("fma.rn.f32x2 %0, %1, %2, %0;" : "+l"(d) : "l"(a), "l"(b));
}

// ---------------------------------------------------------------------------
// GEMM pass: 128 rows x 128 cols per block, 256 threads.
// ---------------------------------------------------------------------------
template<bool SC>
__device__ __forceinline__ void mma_pass2(const float* __restrict__ A, int K,
                                          const float* __restrict__ Ws,
                                          u64t* As, int row0, int tid,
                                          int tr, int tc2, u64t acc[8][4],
                                          float ascale) {
    float4 pre[2];
#pragma unroll
    for (int it = 0; it < 2; it++) {
        int idx = tid + it*256; int lr = idx >> 2, lc = (idx & 3) * 4;
        pre[it] = *(const float4*)(A + (size_t)(row0 + lr)*K + lc);
    }
    for (int k0 = 0; k0 < K; k0 += 16) {
        __syncthreads();
#pragma unroll
        for (int it = 0; it < 2; it++) {
            int idx = tid + it*256; int lr = idx >> 2, lc = (idx & 3) * 4;
            float4 v = pre[it];
            if (SC) { v.x *= ascale; v.y *= ascale; v.z *= ascale; v.w *= ascale; }
            As[lr*17 + lc + 0] = pk2(v.x, v.x);
            As[lr*17 + lc + 1] = pk2(v.y, v.y);
            As[lr*17 + lc + 2] = pk2(v.z, v.z);
            As[lr*17 + lc + 3] = pk2(v.w, v.w);
        }
        __syncthreads();
        if (k0 + 16 < K) {
#pragma unroll
            for (int it = 0; it < 2; it++) {
                int idx = tid + it*256; int lr = idx >> 2, lc = (idx & 3) * 4;
                pre[it] = *(const float4*)(A + (size_t)(row0 + lr)*K + k0 + 16 + lc);
            }
        }
#pragma unroll
        for (int kk = 0; kk < 16; kk++) {
            const float* wrow = Ws + (k0 + kk)*128;
            u64t wv[4];
#pragma unroll
            for (int jp = 0; jp < 4; jp++)
                wv[jp] = *(const u64t*)(wrow + tc2 + 32*jp);
#pragma unroll
            for (int i = 0; i < 8; i++) {
                u64t ap = As[(tr + 16*i)*17 + kk];
#pragma unroll
                for (int jp = 0; jp < 4; jp++) fma2(acc[i][jp], ap, wv[jp]);
            }
        }
    }
}

__device__ __forceinline__ void acc_store(u64t acc[8][4], float* __restrict__ out,
                                          int row0, int tr, int tc2, int relu_flag) {
#pragma unroll
    for (int i = 0; i < 8; i++) {
        int row = row0 + tr + 16*i;
#pragma unroll
        for (int jp = 0; jp < 4; jp++) {
            int cb = tc2 + 32*jp;
            float lo, hi; upk2(acc[i][jp], lo, hi);
            if (relu_flag) { lo = fmaxf(lo, 0.f); hi = fmaxf(hi, 0.f); }
            out[(size_t)row*128 + cb]     = lo;
            out[(size_t)row*128 + cb + 1] = hi;
        }
    }
}

__device__ __forceinline__ void gemm_body(
        const float* __restrict__ A1, const float* __restrict__ W1, int K1,
        const float* __restrict__ A2, const float* __restrict__ W2, int K2,
        const float* __restrict__ A3, const float* __restrict__ W3, int K3,
        const float* __restrict__ bias,
        const float* __restrict__ rowscale,
        const float* __restrict__ rowvec,
        int relu_flag, float* __restrict__ out,
        int blk, float* sm) {
    float* Ws1 = sm;
    float* Ws2 = Ws1 + K1*128;
    float* Ws3 = Ws2 + K2*128;
    u64t*  As  = (u64t*)(Ws3 + K3*128);

    const int tid = threadIdx.x;
    const int tr = tid >> 4, tc2 = (tid & 15) * 2;
    const int row0 = blk * 128;

    for (int i = tid*4; i < K1*128; i += 1024) *(float4*)(Ws1+i) = *(const float4*)(W1+i);
    if (A2) for (int i = tid*4; i < K2*128; i += 1024) *(float4*)(Ws2+i) = *(const float4*)(W2+i);
    if (A3) for (int i = tid*4; i < K3*128; i += 1024) *(float4*)(Ws3+i) = *(const float4*)(W3+i);

    u64t acc[8][4];
#pragma unroll
    for (int i = 0; i < 8; i++)
#pragma unroll
        for (int j = 0; j < 4; j++) acc[i][j] = 0ull;

    mma_pass2<false>(A1, K1, Ws1, As, row0, tid, tr, tc2, acc, 1.f);
    if (A2) mma_pass2<false>(A2, K2, Ws2, As, row0, tid, tr, tc2, acc, 1.f);
    if (A3) mma_pass2<false>(A3, K3, Ws3, As, row0, tid, tr, tc2, acc, 1.f);

#pragma unroll
    for (int i = 0; i < 8; i++) {
        int row = row0 + tr + 16*i;
        float rs = rowscale ? rowscale[row] : 0.f;
#pragma unroll
        for (int jp = 0; jp < 4; jp++) {
            int cb = tc2 + 32*jp;
            float lo, hi; upk2(acc[i][jp], lo, hi);
            if (bias)   { lo += bias[cb];        hi += bias[cb+1]; }
            if (rowvec) { lo += rs * rowvec[cb]; hi += rs * rowvec[cb+1]; }
            if (relu_flag) { lo = fmaxf(lo, 0.f); hi = fmaxf(hi, 0.f); }
            out[(size_t)row*128 + cb]     = lo;
            out[(size_t)row*128 + cb + 1] = hi;
        }
    }
}

// ---------------------------------------------------------------------------
// nm body: scores = xf@Was + bs, softmax over centroids. 64 nodes, 256 thr.
// ---------------------------------------------------------------------------
__device__ __forceinline__ void nm_body(const float* __restrict__ xf, int n0,
                                        float* sm) {
    float* xs  = sm;            // 64*65
    float* ss  = xs + 64*65;    // 512
    float* Ws  = ss + 512;      // 512
    float* bss = Ws + 512;      // 8
    int tid = threadIdx.x;

    for (int i = tid; i < 64*64; i += 256) {
        int rw = i >> 6, k = i & 63;
        xs[rw*65 + k] = xf[(size_t)(n0 + rw)*64 + k];
    }
    for (int i = tid; i < 64*8; i += 256) Ws[i] = g_Was[i];
    if (tid < 8) bss[tid] = g_bs[tid];
    __syncthreads();

    int node = tid >> 2, q = tid & 3;
    float s0 = bss[q], s1 = bss[q + 4];
    for (int k = 0; k < 64; k++) {
        float a = xs[node*65 + k];
        s0 = fmaf(a, Ws[k*8 + q], s0);
        s1 = fmaf(a, Ws[k*8 + q + 4], s1);
    }
    ss[node*8 + q]     = s0;
    ss[node*8 + q + 4] = s1;
    __syncthreads();

    if (tid < 128) {
        int nd = tid >> 1, r = tid & 1;
        float v[4];
#pragma unroll
        for (int c = 0; c < 4; c++) v[c] = ss[nd*8 + c*2 + r];
        float m = fmaxf(fmaxf(v[0], v[1]), fmaxf(v[2], v[3]));
        float e[4], sum = 0.f;
#pragma unroll
        for (int c = 0; c < 4; c++) { e[c] = expf(v[c] - m); sum += e[c]; }
        float inv = 1.f / sum;
        int n = n0 + nd;
#pragma unroll
        for (int c = 0; c < 4; c++)
            g_nm[(size_t)(r*4 + c)*NN + n] = e[c] * inv;
    }
}

// ---------------------------------------------------------------------------
// MEGA1: blocks 0-255 h-GEMM, 256-767 nm.
// ---------------------------------------------------------------------------
__global__ void __launch_bounds__(256, 2)
mega1(const float* __restrict__ x_feat) {
    extern __shared__ float sm[];
    int b = blockIdx.x;
    if (b < 256) {
        gemm_body(x_feat, g_Wab, 64, nullptr, nullptr, 0, nullptr, nullptr, 0,
                  g_biash, nullptr, nullptr, 1, g_h, b, sm);
    } else {
        nm_body(x_feat, (b - 256) * 64, sm);
    }
}

// ---------------------------------------------------------------------------
// MEGA2: blocks 0-255 Z-GEMM (K=144);
// blocks 256-279: hcent partial GEMMs (hb = t&7, p = t>>3):
//   p0: bcxf(K=64)@WaWbc + denr*baWbc ; p1: (ccraw/max)@Wcc ; p2: cx@Wsc.
// ---------------------------------------------------------------------------
__global__ void __launch_bounds__(256, 2)
mega2(const float* __restrict__ x_feat,
      const float* __restrict__ Wcc_, const float* __restrict__ Wsc) {
    extern __shared__ float sm[];
    int b = blockIdx.x;
    if (b < 256) {
        gemm_body(g_aggxf, g_Wawbb, 64, x_feat, g_Wasb, 64, g_aggea, g_W3, 16,
                  g_biasz, g_deg, g_babb, 0, g_Z, b, sm);
        return;
    }
    const int t = b - 256;                 // 0..23
    const int hb = t & 7, p = t >> 3;
    const int tid = threadIdx.x;
    const int tr = tid >> 4, tc2 = (tid & 15) * 2;

    if (p == 0) {
        gemm_body(g_bcxf, g_WaWbc, 64, nullptr, nullptr, 0, nullptr, nullptr, 0,
                  nullptr, g_denr, g_baWbc, 0, g_hp, hb, sm);
    } else {
        float* Ws = sm;
        u64t*  As = (u64t*)(sm + 128*128);
        const int row0 = hb * 128;
        const float* Wsel = (p == 1) ? Wcc_ : Wsc;
        const float* Asel = (p == 1) ? g_ccraw : g_cx;
        const float ascale = (p == 1)
            ? 1.f / (__uint_as_float(g_maxbits) + 1e-9f) : 1.f;
        for (int i = tid*4; i < 128*128; i += 1024)
            *(float4*)(Ws+i) = *(const float4*)(Wsel+i);
        u64t acc[8][4];
#pragma unroll
        for (int i = 0; i < 8; i++)
#pragma unroll
            for (int j = 0; j < 4; j++) acc[i][j] = 0ull;
        mma_pass2<true>(Asel, 128, Ws, As, row0, tid, tr, tc2, acc, ascale);
        acc_store(acc, g_hp + (size_t)p*131072, row0, tr, tc2, 0);
    }
}

// ---------------------------------------------------------------------------
// Parallel weight precompute + counters reset.  grid = 277 x 128.
// ---------------------------------------------------------------------------
__global__ void prep_big(const float* __restrict__ Wa, const float* __restrict__ ba,
                         const float* __restrict__ Wb2c, const float* __restrict__ Wsb,
                         const float* __restrict__ Wbb, const float* __restrict__ We,
                         const float* __restrict__ Wbc, const float* __restrict__ Wscore) {
    int b = blockIdx.x, d = threadIdx.x;
    if (b < 64) {
        float a = 0.f;
        for (int k = 0; k < 128; k++) a = fmaf(Wa[b*128+k], Wb2c[k*128+d], a);
        g_Wab[b*128+d] = a;
    } else if (b < 128) {
        int f = b - 64; float a = 0.f;
        for (int k = 0; k < 128; k++) a = fmaf(Wa[f*128+k], Wsb[k*128+d], a);
        g_Wasb[f*128+d] = a;
    } else if (b < 144) {
        int q = b - 128; float a = 0.f;
        for (int k = 0; k < 128; k++) a = fmaf(We[q*128+k], Wbb[k*128+d], a);
        g_W3[q*128+d] = a;
    } else if (b < 208) {
        int f = b - 144; float a = 0.f;
        for (int k = 0; k < 128; k++) a = fmaf(Wa[f*128+k], Wbb[k*128+d], a);
        g_Wawbb[f*128+d] = a;
    } else if (b < 272) {
        int f = b - 208; float a = 0.f;
        for (int k = 0; k < 128; k++) a = fmaf(Wa[f*128+k], Wbc[k*128+d], a);
        g_WaWbc[f*128+d] = a;
    } else if (b == 272) {
        float a = 0.f;
        for (int k = 0; k < 128; k++) a = fmaf(ba[k], Wb2c[k*128+d], a);
        g_biash[d] = a;
    } else if (b == 273) {
        float a = 0.f;
        for (int k = 0; k < 128; k++) a = fmaf(ba[k], Wsb[k*128+d], a);
        g_biasz[d] = a;
    } else if (b == 274) {
        float a = 0.f;
        for (int k = 0; k < 128; k++) a = fmaf(ba[k], Wbb[k*128+d], a);
        g_babb[d] = a;
        if (d == 0) g_maxbits = 0u;
    } else if (b == 275) {
        float a = 0.f;
        for (int k = 0; k < 128; k++) a = fmaf(ba[k], Wbc[k*128+d], a);
        g_baWbc[d] = a;
    } else {
        for (int o = d; o < 520; o += 128) {
            int r = o >> 3, q = o & 7;
            const float* L = (r < 64) ? (Wa + r*128) : ba;
            float a = 0.f;
            for (int k = 0; k < 128; k++) a = fmaf(L[k], Wscore[k*8+q], a);
            if (r < 64) g_Was[r*8+q] = a; else g_bs[q] = a;
        }
    }
}

// ---------------------------------------------------------------------------
// Per-graph fused kernel.  1 block / graph, 1024 threads, one edge / thread.
// ---------------------------------------------------------------------------
__global__ void __launch_bounds__(1024)
graph_kernel(const float* __restrict__ xf,
             const float* __restrict__ edge_attr,
             const int* __restrict__ ei,
             const float* __restrict__ Wedge) {
    extern __shared__ float smf[];
    float* nm_sm    = smf;               // 2048
    float* srcw     = nm_sm + 2048;      // 2048
    float* ea_sm    = srcw + 2048;       // 16384  (reused later as cx_sm)
    float* wnum_c   = ea_sm + 16384;     // 8192   (reused later as We_sm)
    float* numh_sm  = wnum_c + 8192;     // 1024
    float* bcxf_sm  = numh_sm + 1024;    // 512
    float* red_sm   = bcxf_sm + 512;     // 1024
    float* numea_sm = red_sm + 1024;     // 128
    float* w_sm     = numea_sm + 128;    // 24
    float* den_sm   = w_sm + 24;         // 8
    float* denr_sm  = den_sm + 8;        // 8
    int* sl  = (int*)(denr_sm + 8);      // 1024
    int* dl  = sl + 1024;                // 1024
    int* deg = dl + 1024;                // 256
    int* off = deg + 256;                // 257
    int* cur = off + 257;                // 256
    int* csr = cur + 256;                // 1024

    float* cx_sm = ea_sm;                // alias (free by cx phase)
    float* We_sm = wnum_c;               // alias (free by cx phase)

    const int g = blockIdx.x;
    const int tid = threadIdx.x;
    const int gb = g * PN;
    const int ge = g * EPG;

    if (tid < PN) deg[tid] = 0;
    if (tid < 20) w_sm[tid] = 0.f;
    if (tid < 512) bcxf_sm[tid] = 0.f;
    for (int i = tid; i < 2048; i += 1024) {
        srcw[i] = 0.f;
        nm_sm[i] = g_nm[(size_t)(i >> 8)*NN + gb + (i & 255)];
    }
    __syncthreads();

    // ---- edge pass: one edge per thread ----
    float wp[20];
    {
        const int e = tid;
        int s = ei[ge + e] - gb;
        int d = ei[NE + ge + e] - gb;
        sl[e] = s; dl[e] = d;
        atomicAdd(&deg[d], 1);
        const float4* earow = (const float4*)(edge_attr + (size_t)(ge + e)*16);
        float4* eadst = (float4*)(ea_sm + e*16);
        eadst[0] = earow[0]; eadst[1] = earow[1];
        eadst[2] = earow[2]; eadst[3] = earow[3];

        float ns[8], nd[8];
#pragma unroll
        for (int rc = 0; rc < 8; rc++) {
            ns[rc] = nm_sm[rc*256 + s];
            nd[rc] = nm_sm[rc*256 + d];
            float wv = nd[rc]*nd[rc]*ns[rc];
            wnum_c[e*8 + rc] = wv;
            atomicAdd(&srcw[rc*256 + s], wv);
        }
#pragma unroll
        for (int r = 0; r < 2; r++) {
            int b = r*4, w0 = r*10;
            wp[w0+0] = ns[b+0]*nd[b+1];
            wp[w0+1] = ns[b+0]*nd[b+2];
            wp[w0+2] = ns[b+0]*nd[b+3];
            wp[w0+3] = ns[b+1]*nd[b+2];
            wp[w0+4] = ns[b+1]*nd[b+3];
            wp[w0+5] = ns[b+2]*nd[b+3];
#pragma unroll
            for (int c = 0; c < 4; c++) wp[w0+6+c] = ns[b+c]*nd[b+c];
        }
    }
#pragma unroll
    for (int p = 0; p < 20; p++)
        for (int o = 16; o > 0; o >>= 1)
            wp[p] += __shfl_down_sync(0xffffffffu, wp[p], o);
    if ((tid & 31) == 0)
#pragma unroll
        for (int p = 0; p < 20; p++) atomicAdd(&w_sm[p], wp[p]);
    __syncthreads();

    // ---- numea partials ----
    {
        const int eh = tid >> 7, rcb = (tid >> 4) & 7, qb = tid & 15;
        float nacc = 0.f;
        for (int el = eh*128; el < eh*128 + 128; el++)
            nacc = fmaf(wnum_c[el*8 + rcb], ea_sm[el*16 + qb], nacc);
        red_sm[tid] = nacc;
    }
    __syncthreads();
    if (tid < 256) {
        int rc = tid >> 5, lane = tid & 31;
        float s = 0.f;
        for (int n = lane; n < PN; n += 32) s += nm_sm[rc*256 + n];
        for (int o = 16; o > 0; o >>= 1) s += __shfl_down_sync(0xffffffffu, s, o);
        if (lane == 0) { denr_sm[rc] = s; den_sm[rc] = s + 1e-6f; }
    }
    if (tid >= 512 && tid < 640) {
        int t = tid - 512;
        float v = 0.f;
#pragma unroll
        for (int j = 0; j < 8; j++) v += red_sm[t + j*128];
        numea_sm[t] = v;
    }

    // ---- CSR scan (warp 0) ----
    if (tid < 32) {
        int run = 0;
        for (int seg = 0; seg < 8; seg++) {
            int dv = deg[seg*32 + tid];
            int v = dv;
#pragma unroll
            for (int o = 1; o < 32; o <<= 1) {
                int t = __shfl_up_sync(0xffffffffu, v, o);
                if ((tid & 31) >= o) v += t;
            }
            off[seg*32 + tid] = run + v - dv;
            run += __shfl_sync(0xffffffffu, v, 31);
        }
        if (tid == 31) off[PN] = run;
    }
    __syncthreads();
    if (tid < PN) cur[tid] = off[tid];
    __syncthreads();
    {
        int pos = atomicAdd(&cur[dl[tid]], 1);
        csr[pos] = tid;
    }
    __syncthreads();

    if (tid < PN) g_deg[gb + tid] = (float)deg[tid];

    for (int i = tid; i < PN*16; i += 1024) {
        int nl = i >> 4, q = i & 15;
        float a = 0.f;
        int e0 = off[nl], e1 = off[nl + 1];
        for (int ii = e0; ii < e1; ii++)
            a += ea_sm[csr[ii]*16 + q];
        g_aggea[(size_t)(gb + nl)*16 + q] = a;
    }

    // aggxf (CSR gather) + bcxf (nm-weighted xf sums), thread = (grp16, d64)
    {
        const int d64 = tid & 63, grp = tid >> 6;
        float bl[8];
#pragma unroll
        for (int rc = 0; rc < 8; rc++) bl[rc] = 0.f;
        for (int nl = grp; nl < PN; nl += 16) {
            float xv = xf[(size_t)(gb + nl)*64 + d64];
#pragma unroll
            for (int rc = 0; rc < 8; rc++)
                bl[rc] = fmaf(nm_sm[rc*256 + nl], xv, bl[rc]);
            float a = 0.f;
            int e0 = off[nl], e1 = off[nl + 1];
            for (int ii = e0; ii < e1; ii++)
                a += xf[(size_t)(gb + sl[csr[ii]])*64 + d64];
            g_aggxf[(size_t)(gb + nl)*64 + d64] = a;
        }
#pragma unroll
        for (int rc = 0; rc < 8; rc++)
            atomicAdd(&bcxf_sm[rc*64 + d64], bl[rc]);
    }

    // ---- vector phase: numh only ----
    const int d = tid & 127, grp8 = tid >> 7;
    float numa[8];
#pragma unroll
    for (int rc = 0; rc < 8; rc++) numa[rc] = 0.f;

    for (int nl = grp8; nl < PN; nl += 8) {
        float hv = g_h[(size_t)(gb + nl)*128 + d];
#pragma unroll
        for (int rc = 0; rc < 8; rc++)
            numa[rc] = fmaf(nm_sm[rc*256 + nl] + srcw[rc*256 + nl], hv, numa[rc]);
    }
    __syncthreads();
    for (int gg = 0; gg < 8; gg++) {
        if (grp8 == gg) {
            if (gg == 0)
#pragma unroll
                for (int rc = 0; rc < 8; rc++) numh_sm[rc*128 + d] = numa[rc];
            else
#pragma unroll
                for (int rc = 0; rc < 8; rc++) numh_sm[rc*128 + d] += numa[rc];
        }
        __syncthreads();
    }

    // write bcxf + denr
    if (tid < 512) {
        int rc = tid >> 6, q = tid & 63;
        int r = rc >> 2, ci = rc & 3;
        g_bcxf[((size_t)(r*NG + g)*4 + ci)*64 + q] = bcxf_sm[tid];
    }
    if (tid < 8) {
        int r = tid >> 2, ci = tid & 3;
        g_denr[(size_t)(r*NG + g)*4 + ci] = denr_sm[tid];
    }

    // ---- cx / ccraw phase (1024 threads = 8 rc x 128 d) ----
    {
        const int rc = tid >> 7, dd = tid & 127;
        const int r = rc >> 2, ci = rc & 3;
        for (int i = tid; i < 2048; i += 1024) We_sm[i] = Wedge[i];
        __syncthreads();
        float v = numh_sm[rc*128 + dd];
#pragma unroll
        for (int q = 0; q < 16; q++)
            v = fmaf(numea_sm[rc*16 + q], We_sm[q*128 + dd], v);
        v /= den_sm[rc];
        cx_sm[rc*128 + dd] = v;
        g_cx[((size_t)(r*NG + g)*4 + ci)*128 + dd] = v;
        __syncthreads();
        const int pidx[4][4] = { {6,0,1,2}, {0,7,3,4}, {1,3,8,5}, {2,4,5,9} };
        float a = 0.f;
#pragma unroll
        for (int j = 0; j < 4; j++) {
            float w = w_sm[r*10 + pidx[ci][j]];
            if (ci == j) w *= 0.5f;
            a = fmaf(w, cx_sm[(r*4 + j)*128 + dd], a);
        }
        g_ccraw[((size_t)(r*NG + g)*4 + ci)*128 + dd] = a;
    }

    if (tid < 32) {
        const int pidx[4][4] = { {6,0,1,2}, {0,7,3,4}, {1,3,8,5}, {2,4,5,9} };
        int r = tid >> 4, idx = tid & 15;
        int i = idx >> 2, j = idx & 3;
        float v = w_sm[r*10 + pidx[i][j]];
        if (i == j) v *= 0.5f;
        float m = v;
        for (int o = 16; o > 0; o >>= 1)
            m = fmaxf(m, __shfl_down_sync(0xffffffffu, m, o));
        if (tid == 0) atomicMax(&g_maxbits, __float_as_uint(m));
    }
}

// ---------------------------------------------------------------------------
// Final fused: hcw = relu(hp0+hp1+hp2)@Wcb (in-block, per graph);
// node = mean_r relu(Z + Sum_c nm*hcw); pool; heads.  grid = NG, 1024 thr.
// ---------------------------------------------------------------------------
__global__ void __launch_bounds__(1024)
final_kernel(const float* __restrict__ Wcb,
             const float* __restrict__ W_inter,
             const float* __restrict__ b_inter,
             const float* __restrict__ W_out,
             const float* __restrict__ b_out,
             float* __restrict__ out) {
    extern __shared__ float sm[];
    float* Wcb_s = sm;             // 16384
    float* hc    = Wcb_s + 16384;  // 1024
    float* hcw   = hc + 1024;      // 1024
    float* nm_s  = hcw + 1024;     // 2048
    float* red   = nm_s + 2048;    // 1024
    float* gs    = red + 1024;     // 128
    float* emb   = gs + 128;       // 128

    int g = blockIdx.x, tid = threadIdx.x;

    for (int i = tid*4; i < 16384; i += 4096)
        *(float4*)(Wcb_s + i) = *(const float4*)(Wcb + i);
    {
        int rc = tid >> 7, k = tid & 127;
        int r = rc >> 2, c = rc & 3;
        size_t o = ((size_t)(r*NG + g)*4 + c)*128 + k;
        float v = g_hp[o] + g_hp[131072 + o] + g_hp[262144 + o];
        hc[tid] = fmaxf(v, 0.f);
    }
    for (int i = tid; i < 2048; i += 1024)
        nm_s[i] = g_nm[(size_t)(i >> 8)*NN + g*PN + (i & 255)];
    __syncthreads();

    // hcw[rc*128+d] = sum_k hc[rc*128+k] * Wcb[k*128+d]
    {
        int rc = tid >> 7, d = tid & 127;
        float a = 0.f;
#pragma unroll 4
        for (int k = 0; k < 128; k++)
            a = fmaf(hc[rc*128 + k], Wcb_s[k*128 + d], a);
        hcw[tid] = a;
    }
    __syncthreads();

    int d = tid & 127, q8 = tid >> 7;
    float acc = 0.f;
    for (int nl = q8; nl < PN; nl += 8) {
        float z = g_Z[(size_t)(g*PN + nl)*128 + d];
        float y0 = 0.f, y1 = 0.f;
#pragma unroll
        for (int c = 0; c < 4; c++) {
            y0 = fmaf(nm_s[c*256 + nl],       hcw[c*128 + d],       y0);
            y1 = fmaf(nm_s[(4 + c)*256 + nl], hcw[512 + c*128 + d], y1);
        }
        acc += 0.5f * (fmaxf(z + y0, 0.f) + fmaxf(z + y1, 0.f));
    }
    red[tid] = acc;
    __syncthreads();
    if (tid < 128) {
        float s = 0.f;
#pragma unroll
        for (int j = 0; j < 8; j++) s += red[tid + j*128];
        gs[tid] = s * (1.0f / PN);
    }
    __syncthreads();
    if (tid < 128) {
        float e = b_inter[tid];
        for (int k = 0; k < 128; k++) e = fmaf(gs[k], W_inter[k*128 + tid], e);
        emb[tid] = e;
    }
    __syncthreads();
    if (tid < OUTD) {
        float o = b_out[tid];
        for (int k = 0; k < 128; k++) o = fmaf(emb[k], W_out[k*OUTD + tid], o);
        out[g*OUTD + tid] = o;
    }
}

// ---------------------------------------------------------------------------
extern "C" void kernel_launch(void* const* d_in, const int* in_sizes, int n_in,
                              void* d_out, int out_size) {
    const float* x_feat    = (const float*)d_in[0];
    const float* edge_attr = (const float*)d_in[1];
    const float* W_atom    = (const float*)d_in[2];
    const float* b_atom    = (const float*)d_in[3];
    const float* W_score   = (const float*)d_in[4];
    const float* W_edge    = (const float*)d_in[5];
    const float* W_b2c     = (const float*)d_in[6];
    const float* W_bb      = (const float*)d_in[7];
    const float* W_bc      = (const float*)d_in[8];
    const float* W_cb      = (const float*)d_in[9];
    const float* W_cc      = (const float*)d_in[10];
    const float* W_sb      = (const float*)d_in[11];
    const float* W_sc      = (const float*)d_in[12];
    const float* W_inter   = (const float*)d_in[13];
    const float* b_inter   = (const float*)d_in[14];
    const float* W_out     = (const float*)d_in[15];
    const float* b_out     = (const float*)d_in[16];
    const int*   edge_index= (const int*)d_in[17];
    float* out = (float*)d_out;

    cudaFuncSetAttribute(mega1, cudaFuncAttributeMaxDynamicSharedMemorySize, 52000);
    cudaFuncSetAttribute(mega2, cudaFuncAttributeMaxDynamicSharedMemorySize, 95000);
    cudaFuncSetAttribute(graph_kernel, cudaFuncAttributeMaxDynamicSharedMemorySize, 145000);
    cudaFuncSetAttribute(final_kernel, cudaFuncAttributeMaxDynamicSharedMemorySize, 90000);

    const size_t smA = 128*17*8;   // packed u64 A tile = 17408

    // 1. fused weights + counter reset
    prep_big<<<277, 128>>>(W_atom, b_atom, W_b2c, W_sb, W_bb, W_edge, W_bc, W_score);
    // 2. h-GEMM + nm in one launch
    mega1<<<768, 256, 64*512 + smA>>>(x_feat);
    // 3. per-graph fused pass (aggea/aggxf/deg, numh, bcxf, cx, ccraw)
    graph_kernel<<<NG, 1024, 141000>>>(x_feat, edge_attr, edge_index, W_edge);
    // 4. Z-GEMM + hcent partials in one launch (280 blocks, one wave)
    mega2<<<280, 256, (64+64+16)*512 + smA>>>(x_feat, W_cc, W_sc);
    // 5. fused hcw + Y + relu + mean + pool + heads
    final_kernel<<<NG, 1024, 88000>>>(W_cb, W_inter, b_inter, W_out, b_out, out);
}

// round 13
// speedup vs baseline: 1.6784x; 1.0113x over previous
#include <cuda_runtime.h>
#include <math.h>

#define NG   128
#define PN   256
#define EPG  1024
#define NN   (NG*PN)     // 32768
#define NE   (NG*EPG)    // 131072
#define DD   128
#define OUTD 10

// ---------------- device scratch ----------------
__device__ float g_h[NN*DD];
__device__ float g_nm[8*NN];              // [(r*4+c)*NN + n]
__device__ float g_aggxf[NN*64];
__device__ float g_deg[NN];
__device__ float g_aggea[NN*16];
__device__ float g_bcxf[2*NG*4*64];       // 1024 x 64:  sum_n nm * xf
__device__ float g_denr[2*NG*4];          // raw nm sums (no eps)
__device__ float g_cx[2*NG*4*DD];         // cent_x, 1024 x 128
__device__ float g_ccraw[2*NG*4*DD];      // Wgraw @ cent_x (unnormalized)
__device__ float g_hp[3*2*NG*4*DD];       // hcent partials (3 x 1024 x 128)
__device__ unsigned int g_maxbits;
__device__ float g_Z[NN*DD];
// fused weights
__device__ float g_Wab[64*128];           // Wa@W_b2c
__device__ float g_Wasb[64*128];          // Wa@W_sb
__device__ float g_Wawbb[64*128];         // Wa@W_bb
__device__ float g_WaWbc[64*128];         // Wa@W_bc
__device__ float g_W3[16*128];            // We@W_bb
__device__ float g_biash[128];            // ba@W_b2c
__device__ float g_biasz[128];            // ba@W_sb
__device__ float g_babb[128];             // ba@W_bb
__device__ float g_baWbc[128];            // ba@W_bc
__device__ float g_Was[64*8];             // Wa@W_score
__device__ float g_bs[8];                 // ba@W_score

// ---------------- packed f32x2 helpers ----------------
typedef unsigned long long u64t;
__device__ __forceinline__ u64t pk2(float lo, float hi) {
    u64t r; asm("mov.b64 %0, {%1,%2};" : "=l"(r) : "f"(lo), "f"(hi)); return r;
}
__device__ __forceinline__ void upk2(u64t v, float& lo, float& hi) {
    asm("mov.b64 {%0,%1}, %2;" : "=f"(lo), "=f"(hi) : "l"(v));
}
__device__ __forceinline__ void fma2(u64t& d, u64t a, u64t b) {
    asm("fma.rn.f32x2 %0, %1, %2, %0;" : "+l"(d) : "l"(a), "l"(b));
}

// ---------------------------------------------------------------------------
// GEMM pass: 128 rows x 128 cols per block, 256 threads.
// ---------------------------------------------------------------------------
template<bool SC>
__device__ __forceinline__ void mma_pass2(const float* __restrict__ A, int K,
                                          const float* __restrict__ Ws,
                                          u64t* As, int row0, int tid,
                                          int tr, int tc2, u64t acc[8][4],
                                          float ascale) {
    float4 pre[2];
#pragma unroll
    for (int it = 0; it < 2; it++) {
        int idx = tid + it*256; int lr = idx >> 2, lc = (idx & 3) * 4;
        pre[it] = *(const float4*)(A + (size_t)(row0 + lr)*K + lc);
    }
    for (int k0 = 0; k0 < K; k0 += 16) {
        __syncthreads();
#pragma unroll
        for (int it = 0; it < 2; it++) {
            int idx = tid + it*256; int lr = idx >> 2, lc = (idx & 3) * 4;
            float4 v = pre[it];
            if (SC) { v.x *= ascale; v.y *= ascale; v.z *= ascale; v.w *= ascale; }
            As[lr*17 + lc + 0] = pk2(v.x, v.x);
            As[lr*17 + lc + 1] = pk2(v.y, v.y);
            As[lr*17 + lc + 2] = pk2(v.z, v.z);
            As[lr*17 + lc + 3] = pk2(v.w, v.w);
        }
        __syncthreads();
        if (k0 + 16 < K) {
#pragma unroll
            for (int it = 0; it < 2; it++) {
                int idx = tid + it*256; int lr = idx >> 2, lc = (idx & 3) * 4;
                pre[it] = *(const float4*)(A + (size_t)(row0 + lr)*K + k0 + 16 + lc);
            }
        }
#pragma unroll
        for (int kk = 0; kk < 16; kk++) {
            const float* wrow = Ws + (k0 + kk)*128;
            u64t wv[4];
#pragma unroll
            for (int jp = 0; jp < 4; jp++)
                wv[jp] = *(const u64t*)(wrow + tc2 + 32*jp);
            u64t ap[8];
#pragma unroll
            for (int i = 0; i < 8; i++)
                ap[i] = As[(tr + 16*i)*17 + kk];
#pragma unroll
            for (int i = 0; i < 8; i++)
#pragma unroll
                for (int jp = 0; jp < 4; jp++) fma2(acc[i][jp], ap[i], wv[jp]);
        }
    }
}

__device__ __forceinline__ void acc_store(u64t acc[8][4], float* __restrict__ out,
                                          int row0, int tr, int tc2, int relu_flag) {
#pragma unroll
    for (int i = 0; i < 8; i++) {
        int row = row0 + tr + 16*i;
#pragma unroll
        for (int jp = 0; jp < 4; jp++) {
            int cb = tc2 + 32*jp;
            float lo, hi; upk2(acc[i][jp], lo, hi);
            if (relu_flag) { lo = fmaxf(lo, 0.f); hi = fmaxf(hi, 0.f); }
            out[(size_t)row*128 + cb]     = lo;
            out[(size_t)row*128 + cb + 1] = hi;
        }
    }
}

__device__ __forceinline__ void gemm_body(
        const float* __restrict__ A1, const float* __restrict__ W1, int K1,
        const float* __restrict__ A2, const float* __restrict__ W2, int K2,
        const float* __restrict__ A3, const float* __restrict__ W3, int K3,
        const float* __restrict__ bias,
        const float* __restrict__ rowscale,
        const float* __restrict__ rowvec,
        int relu_flag, float* __restrict__ out,
        int blk, float* sm) {
    float* Ws1 = sm;
    float* Ws2 = Ws1 + K1*128;
    float* Ws3 = Ws2 + K2*128;
    u64t*  As  = (u64t*)(Ws3 + K3*128);

    const int tid = threadIdx.x;
    const int tr = tid >> 4, tc2 = (tid & 15) * 2;
    const int row0 = blk * 128;

    for (int i = tid*4; i < K1*128; i += 1024) *(float4*)(Ws1+i) = *(const float4*)(W1+i);
    if (A2) for (int i = tid*4; i < K2*128; i += 1024) *(float4*)(Ws2+i) = *(const float4*)(W2+i);
    if (A3) for (int i = tid*4; i < K3*128; i += 1024) *(float4*)(Ws3+i) = *(const float4*)(W3+i);

    u64t acc[8][4];
#pragma unroll
    for (int i = 0; i < 8; i++)
#pragma unroll
        for (int j = 0; j < 4; j++) acc[i][j] = 0ull;

    mma_pass2<false>(A1, K1, Ws1, As, row0, tid, tr, tc2, acc, 1.f);
    if (A2) mma_pass2<false>(A2, K2, Ws2, As, row0, tid, tr, tc2, acc, 1.f);
    if (A3) mma_pass2<false>(A3, K3, Ws3, As, row0, tid, tr, tc2, acc, 1.f);

#pragma unroll
    for (int i = 0; i < 8; i++) {
        int row = row0 + tr + 16*i;
        float rs = rowscale ? rowscale[row] : 0.f;
#pragma unroll
        for (int jp = 0; jp < 4; jp++) {
            int cb = tc2 + 32*jp;
            float lo, hi; upk2(acc[i][jp], lo, hi);
            if (bias)   { lo += bias[cb];        hi += bias[cb+1]; }
            if (rowvec) { lo += rs * rowvec[cb]; hi += rs * rowvec[cb+1]; }
            if (relu_flag) { lo = fmaxf(lo, 0.f); hi = fmaxf(hi, 0.f); }
            out[(size_t)row*128 + cb]     = lo;
            out[(size_t)row*128 + cb + 1] = hi;
        }
    }
}

// ---------------------------------------------------------------------------
// MEGA1: pure h-GEMM, 256 blocks (single wave).
// ---------------------------------------------------------------------------
__global__ void __launch_bounds__(256, 2)
mega1(const float* __restrict__ x_feat) {
    extern __shared__ float sm[];
    gemm_body(x_feat, g_Wab, 64, nullptr, nullptr, 0, nullptr, nullptr, 0,
              g_biash, nullptr, nullptr, 1, g_h, blockIdx.x, sm);
}

// ---------------------------------------------------------------------------
// MEGA2: blocks 0-255 Z-GEMM (K=144);
// blocks 256-279: hcent partial GEMMs (hb = t&7, p = t>>3):
//   p0: bcxf(K=64)@WaWbc + denr*baWbc ; p1: (ccraw/max)@Wcc ; p2: cx@Wsc.
// ---------------------------------------------------------------------------
__global__ void __launch_bounds__(256, 2)
mega2(const float* __restrict__ x_feat,
      const float* __restrict__ Wcc_, const float* __restrict__ Wsc) {
    extern __shared__ float sm[];
    int b = blockIdx.x;
    if (b < 256) {
        gemm_body(g_aggxf, g_Wawbb, 64, x_feat, g_Wasb, 64, g_aggea, g_W3, 16,
                  g_biasz, g_deg, g_babb, 0, g_Z, b, sm);
        return;
    }
    const int t = b - 256;                 // 0..23
    const int hb = t & 7, p = t >> 3;
    const int tid = threadIdx.x;
    const int tr = tid >> 4, tc2 = (tid & 15) * 2;

    if (p == 0) {
        gemm_body(g_bcxf, g_WaWbc, 64, nullptr, nullptr, 0, nullptr, nullptr, 0,
                  nullptr, g_denr, g_baWbc, 0, g_hp, hb, sm);
    } else {
        float* Ws = sm;
        u64t*  As = (u64t*)(sm + 128*128);
        const int row0 = hb * 128;
        const float* Wsel = (p == 1) ? Wcc_ : Wsc;
        const float* Asel = (p == 1) ? g_ccraw : g_cx;
        const float ascale = (p == 1)
            ? 1.f / (__uint_as_float(g_maxbits) + 1e-9f) : 1.f;
        for (int i = tid*4; i < 128*128; i += 1024)
            *(float4*)(Ws+i) = *(const float4*)(Wsel+i);
        u64t acc[8][4];
#pragma unroll
        for (int i = 0; i < 8; i++)
#pragma unroll
            for (int j = 0; j < 4; j++) acc[i][j] = 0ull;
        mma_pass2<true>(Asel, 128, Ws, As, row0, tid, tr, tc2, acc, ascale);
        acc_store(acc, g_hp + (size_t)p*131072, row0, tr, tc2, 0);
    }
}

// ---------------------------------------------------------------------------
// Parallel weight precompute + counters reset.  grid = 277 x 128.
// ---------------------------------------------------------------------------
__global__ void prep_big(const float* __restrict__ Wa, const float* __restrict__ ba,
                         const float* __restrict__ Wb2c, const float* __restrict__ Wsb,
                         const float* __restrict__ Wbb, const float* __restrict__ We,
                         const float* __restrict__ Wbc, const float* __restrict__ Wscore) {
    int b = blockIdx.x, d = threadIdx.x;
    if (b < 64) {
        float a = 0.f;
        for (int k = 0; k < 128; k++) a = fmaf(Wa[b*128+k], Wb2c[k*128+d], a);
        g_Wab[b*128+d] = a;
    } else if (b < 128) {
        int f = b - 64; float a = 0.f;
        for (int k = 0; k < 128; k++) a = fmaf(Wa[f*128+k], Wsb[k*128+d], a);
        g_Wasb[f*128+d] = a;
    } else if (b < 144) {
        int q = b - 128; float a = 0.f;
        for (int k = 0; k < 128; k++) a = fmaf(We[q*128+k], Wbb[k*128+d], a);
        g_W3[q*128+d] = a;
    } else if (b < 208) {
        int f = b - 144; float a = 0.f;
        for (int k = 0; k < 128; k++) a = fmaf(Wa[f*128+k], Wbb[k*128+d], a);
        g_Wawbb[f*128+d] = a;
    } else if (b < 272) {
        int f = b - 208; float a = 0.f;
        for (int k = 0; k < 128; k++) a = fmaf(Wa[f*128+k], Wbc[k*128+d], a);
        g_WaWbc[f*128+d] = a;
    } else if (b == 272) {
        float a = 0.f;
        for (int k = 0; k < 128; k++) a = fmaf(ba[k], Wb2c[k*128+d], a);
        g_biash[d] = a;
    } else if (b == 273) {
        float a = 0.f;
        for (int k = 0; k < 128; k++) a = fmaf(ba[k], Wsb[k*128+d], a);
        g_biasz[d] = a;
    } else if (b == 274) {
        float a = 0.f;
        for (int k = 0; k < 128; k++) a = fmaf(ba[k], Wbb[k*128+d], a);
        g_babb[d] = a;
        if (d == 0) g_maxbits = 0u;
    } else if (b == 275) {
        float a = 0.f;
        for (int k = 0; k < 128; k++) a = fmaf(ba[k], Wbc[k*128+d], a);
        g_baWbc[d] = a;
    } else {
        for (int o = d; o < 520; o += 128) {
            int r = o >> 3, q = o & 7;
            const float* L = (r < 64) ? (Wa + r*128) : ba;
            float a = 0.f;
            for (int k = 0; k < 128; k++) a = fmaf(L[k], Wscore[k*8+q], a);
            if (r < 64) g_Was[r*8+q] = a; else g_bs[q] = a;
        }
    }
}

// ---------------------------------------------------------------------------
// Per-graph fused kernel.  1 block / graph, 1024 threads.
// Computes nm (scores+softmax), then aggea/aggxf/deg, numh/denr, bcxf,
// cent_x, ccraw in-block.
// ---------------------------------------------------------------------------
__global__ void __launch_bounds__(1024)
graph_kernel(const float* __restrict__ xf,
             const float* __restrict__ edge_attr,
             const int* __restrict__ ei,
             const float* __restrict__ Wedge) {
    extern __shared__ float smf[];
    float* nm_sm    = smf;               // 2048
    float* srcw     = nm_sm + 2048;      // 2048
    float* ea_sm    = srcw + 2048;       // 16384  (xf stage, then edges, then cx)
    float* wnum_c   = ea_sm + 16384;     // 8192   (scores, then wnum, then We)
    float* numh_sm  = wnum_c + 8192;     // 1024
    float* bcxf_sm  = numh_sm + 1024;    // 512
    float* red_sm   = bcxf_sm + 512;     // 1024
    float* numea_sm = red_sm + 1024;     // 128
    float* was_sm   = numea_sm + 128;    // 520
    float* w_sm     = was_sm + 520;      // 24
    float* den_sm   = w_sm + 24;         // 8
    float* denr_sm  = den_sm + 8;        // 8
    int* sl  = (int*)(denr_sm + 8);      // 1024
    int* dl  = sl + 1024;                // 1024
    int* deg = dl + 1024;                // 256
    int* off = deg + 256;                // 257
    int* cur = off + 257;                // 256
    int* csr = cur + 256;                // 1024

    float* cx_sm = ea_sm;                // alias
    float* We_sm = wnum_c;               // alias

    const int g = blockIdx.x;
    const int tid = threadIdx.x;
    const int gb = g * PN;
    const int ge = g * EPG;

    // ---- nm phase: stage xf tile, scores, softmax ----
    for (int i = tid*4; i < PN*64; i += 4096)
        *(float4*)(ea_sm + i) = *(const float4*)(xf + (size_t)gb*64 + i);
    for (int i = tid; i < 512; i += 1024) was_sm[i] = g_Was[i];
    if (tid < 8) was_sm[512 + tid] = g_bs[tid];
    if (tid < PN) deg[tid] = 0;
    if (tid < 20) w_sm[tid] = 0.f;
    if (tid < 512) bcxf_sm[tid] = 0.f;
    for (int i = tid; i < 2048; i += 1024) srcw[i] = 0.f;
    __syncthreads();
    {
        int node = tid >> 2, q = tid & 3;
        float s0 = was_sm[512 + q], s1 = was_sm[512 + q + 4];
        const float* xrow = ea_sm + node*64;
        for (int k = 0; k < 64; k++) {
            float a = xrow[k];
            s0 = fmaf(a, was_sm[k*8 + q], s0);
            s1 = fmaf(a, was_sm[k*8 + q + 4], s1);
        }
        wnum_c[node*8 + q]     = s0;
        wnum_c[node*8 + q + 4] = s1;
    }
    __syncthreads();
    if (tid < 512) {
        int node = tid >> 1, r = tid & 1;
        float v[4];
#pragma unroll
        for (int c = 0; c < 4; c++) v[c] = wnum_c[node*8 + c*2 + r];
        float m = fmaxf(fmaxf(v[0], v[1]), fmaxf(v[2], v[3]));
        float e[4], sum = 0.f;
#pragma unroll
        for (int c = 0; c < 4; c++) { e[c] = expf(v[c] - m); sum += e[c]; }
        float inv = 1.f / sum;
#pragma unroll
        for (int c = 0; c < 4; c++) {
            float nv = e[c] * inv;
            nm_sm[(r*4 + c)*256 + node] = nv;
            g_nm[(size_t)(r*4 + c)*NN + gb + node] = nv;
        }
    }
    __syncthreads();

    // ---- edge pass: one edge per thread ----
    float wp[20];
    {
        const int e = tid;
        int s = ei[ge + e] - gb;
        int d = ei[NE + ge + e] - gb;
        sl[e] = s; dl[e] = d;
        atomicAdd(&deg[d], 1);
        const float4* earow = (const float4*)(edge_attr + (size_t)(ge + e)*16);
        float4 e0 = earow[0], e1 = earow[1], e2 = earow[2], e3 = earow[3];

        float ns[8], nd[8];
#pragma unroll
        for (int rc = 0; rc < 8; rc++) {
            ns[rc] = nm_sm[rc*256 + s];
            nd[rc] = nm_sm[rc*256 + d];
        }
        __syncthreads();   // all reads of staged xf (ea_sm) done; safe to overwrite
        float4* eadst = (float4*)(ea_sm + e*16);
        eadst[0] = e0; eadst[1] = e1; eadst[2] = e2; eadst[3] = e3;
#pragma unroll
        for (int rc = 0; rc < 8; rc++) {
            float wv = nd[rc]*nd[rc]*ns[rc];
            wnum_c[e*8 + rc] = wv;
            atomicAdd(&srcw[rc*256 + s], wv);
        }
#pragma unroll
        for (int r = 0; r < 2; r++) {
            int b = r*4, w0 = r*10;
            wp[w0+0] = ns[b+0]*nd[b+1];
            wp[w0+1] = ns[b+0]*nd[b+2];
            wp[w0+2] = ns[b+0]*nd[b+3];
            wp[w0+3] = ns[b+1]*nd[b+2];
            wp[w0+4] = ns[b+1]*nd[b+3];
            wp[w0+5] = ns[b+2]*nd[b+3];
#pragma unroll
            for (int c = 0; c < 4; c++) wp[w0+6+c] = ns[b+c]*nd[b+c];
        }
    }
#pragma unroll
    for (int p = 0; p < 20; p++)
        for (int o = 16; o > 0; o >>= 1)
            wp[p] += __shfl_down_sync(0xffffffffu, wp[p], o);
    if ((tid & 31) == 0)
#pragma unroll
        for (int p = 0; p < 20; p++) atomicAdd(&w_sm[p], wp[p]);
    __syncthreads();

    // ---- numea partials ----
    {
        const int eh = tid >> 7, rcb = (tid >> 4) & 7, qb = tid & 15;
        float nacc = 0.f;
        for (int el = eh*128; el < eh*128 + 128; el++)
            nacc = fmaf(wnum_c[el*8 + rcb], ea_sm[el*16 + qb], nacc);
        red_sm[tid] = nacc;
    }
    __syncthreads();
    if (tid < 256) {
        int rc = tid >> 5, lane = tid & 31;
        float s = 0.f;
        for (int n = lane; n < PN; n += 32) s += nm_sm[rc*256 + n];
        for (int o = 16; o > 0; o >>= 1) s += __shfl_down_sync(0xffffffffu, s, o);
        if (lane == 0) { denr_sm[rc] = s; den_sm[rc] = s + 1e-6f; }
    }
    if (tid >= 512 && tid < 640) {
        int t = tid - 512;
        float v = 0.f;
#pragma unroll
        for (int j = 0; j < 8; j++) v += red_sm[t + j*128];
        numea_sm[t] = v;
    }

    // ---- CSR scan (warp 0) ----
    if (tid < 32) {
        int run = 0;
        for (int seg = 0; seg < 8; seg++) {
            int dv = deg[seg*32 + tid];
            int v = dv;
#pragma unroll
            for (int o = 1; o < 32; o <<= 1) {
                int t = __shfl_up_sync(0xffffffffu, v, o);
                if ((tid & 31) >= o) v += t;
            }
            off[seg*32 + tid] = run + v - dv;
            run += __shfl_sync(0xffffffffu, v, 31);
        }
        if (tid == 31) off[PN] = run;
    }
    __syncthreads();
    if (tid < PN) cur[tid] = off[tid];
    __syncthreads();
    {
        int pos = atomicAdd(&cur[dl[tid]], 1);
        csr[pos] = tid;
    }
    __syncthreads();

    if (tid < PN) g_deg[gb + tid] = (float)deg[tid];

    for (int i = tid; i < PN*16; i += 1024) {
        int nl = i >> 4, q = i & 15;
        float a = 0.f;
        int e0 = off[nl], e1 = off[nl + 1];
        for (int ii = e0; ii < e1; ii++)
            a += ea_sm[csr[ii]*16 + q];
        g_aggea[(size_t)(gb + nl)*16 + q] = a;
    }

    // aggxf (CSR gather) + bcxf (nm-weighted xf sums), thread = (grp16, d64)
    {
        const int d64 = tid & 63, grp = tid >> 6;
        float bl[8];
#pragma unroll
        for (int rc = 0; rc < 8; rc++) bl[rc] = 0.f;
        for (int nl = grp; nl < PN; nl += 16) {
            float xv = xf[(size_t)(gb + nl)*64 + d64];
#pragma unroll
            for (int rc = 0; rc < 8; rc++)
                bl[rc] = fmaf(nm_sm[rc*256 + nl], xv, bl[rc]);
            float a = 0.f;
            int e0 = off[nl], e1 = off[nl + 1];
            for (int ii = e0; ii < e1; ii++)
                a += xf[(size_t)(gb + sl[csr[ii]])*64 + d64];
            g_aggxf[(size_t)(gb + nl)*64 + d64] = a;
        }
#pragma unroll
        for (int rc = 0; rc < 8; rc++)
            atomicAdd(&bcxf_sm[rc*64 + d64], bl[rc]);
    }

    // ---- vector phase: numh only ----
    const int d = tid & 127, grp8 = tid >> 7;
    float numa[8];
#pragma unroll
    for (int rc = 0; rc < 8; rc++) numa[rc] = 0.f;

    for (int nl = grp8; nl < PN; nl += 8) {
        float hv = g_h[(size_t)(gb + nl)*128 + d];
#pragma unroll
        for (int rc = 0; rc < 8; rc++)
            numa[rc] = fmaf(nm_sm[rc*256 + nl] + srcw[rc*256 + nl], hv, numa[rc]);
    }
    __syncthreads();
    for (int gg = 0; gg < 8; gg++) {
        if (grp8 == gg) {
            if (gg == 0)
#pragma unroll
                for (int rc = 0; rc < 8; rc++) numh_sm[rc*128 + d] = numa[rc];
            else
#pragma unroll
                for (int rc = 0; rc < 8; rc++) numh_sm[rc*128 + d] += numa[rc];
        }
        __syncthreads();
    }

    // write bcxf + denr
    if (tid < 512) {
        int rc = tid >> 6, q = tid & 63;
        int r = rc >> 2, ci = rc & 3;
        g_bcxf[((size_t)(r*NG + g)*4 + ci)*64 + q] = bcxf_sm[tid];
    }
    if (tid < 8) {
        int r = tid >> 2, ci = tid & 3;
        g_denr[(size_t)(r*NG + g)*4 + ci] = denr_sm[tid];
    }

    // ---- cx / ccraw phase (1024 threads = 8 rc x 128 d) ----
    {
        const int rc = tid >> 7, dd = tid & 127;
        const int r = rc >> 2, ci = rc & 3;
        for (int i = tid; i < 2048; i += 1024) We_sm[i] = Wedge[i];
        __syncthreads();
        float v = numh_sm[rc*128 + dd];
#pragma unroll
        for (int q = 0; q < 16; q++)
            v = fmaf(numea_sm[rc*16 + q], We_sm[q*128 + dd], v);
        v /= den_sm[rc];
        cx_sm[rc*128 + dd] = v;
        g_cx[((size_t)(r*NG + g)*4 + ci)*128 + dd] = v;
        __syncthreads();
        const int pidx[4][4] = { {6,0,1,2}, {0,7,3,4}, {1,3,8,5}, {2,4,5,9} };
        float a = 0.f;
#pragma unroll
        for (int j = 0; j < 4; j++) {
            float w = w_sm[r*10 + pidx[ci][j]];
            if (ci == j) w *= 0.5f;
            a = fmaf(w, cx_sm[(r*4 + j)*128 + dd], a);
        }
        g_ccraw[((size_t)(r*NG + g)*4 + ci)*128 + dd] = a;
    }

    if (tid < 32) {
        const int pidx[4][4] = { {6,0,1,2}, {0,7,3,4}, {1,3,8,5}, {2,4,5,9} };
        int r = tid >> 4, idx = tid & 15;
        int i = idx >> 2, j = idx & 3;
        float v = w_sm[r*10 + pidx[i][j]];
        if (i == j) v *= 0.5f;
        float m = v;
        for (int o = 16; o > 0; o >>= 1)
            m = fmaxf(m, __shfl_down_sync(0xffffffffu, m, o));
        if (tid == 0) atomicMax(&g_maxbits, __float_as_uint(m));
    }
}

// ---------------------------------------------------------------------------
// Final fused: hcw = relu(hp0+hp1+hp2)@Wcb (in-block, per graph);
// node = mean_r relu(Z + Sum_c nm*hcw); pool; heads.  grid = NG, 1024 thr.
// ---------------------------------------------------------------------------
__global__ void __launch_bounds__(1024)
final_kernel(const float* __restrict__ Wcb,
             const float* __restrict__ W_inter,
             const float* __restrict__ b_inter,
             const float* __restrict__ W_out,
             const float* __restrict__ b_out,
             float* __restrict__ out) {
    extern __shared__ float sm[];
    float* Wcb_s = sm;             // 16384
    float* hc    = Wcb_s + 16384;  // 1024
    float* hcw   = hc + 1024;      // 1024
    float* nm_s  = hcw + 1024;     // 2048
    float* red   = nm_s + 2048;    // 1024
    float* gs    = red + 1024;     // 128
    float* emb   = gs + 128;       // 128

    int g = blockIdx.x, tid = threadIdx.x;

    for (int i = tid*4; i < 16384; i += 4096)
        *(float4*)(Wcb_s + i) = *(const float4*)(Wcb + i);
    {
        int rc = tid >> 7, k = tid & 127;
        int r = rc >> 2, c = rc & 3;
        size_t o = ((size_t)(r*NG + g)*4 + c)*128 + k;
        float v = g_hp[o] + g_hp[131072 + o] + g_hp[262144 + o];
        hc[tid] = fmaxf(v, 0.f);
    }
    for (int i = tid; i < 2048; i += 1024)
        nm_s[i] = g_nm[(size_t)(i >> 8)*NN + g*PN + (i & 255)];
    __syncthreads();

    // hcw[rc*128+d] = sum_k hc[rc*128+k] * Wcb[k*128+d]
    {
        int rc = tid >> 7, d = tid & 127;
        float a = 0.f;
#pragma unroll 4
        for (int k = 0; k < 128; k++)
            a = fmaf(hc[rc*128 + k], Wcb_s[k*128 + d], a);
        hcw[tid] = a;
    }
    __syncthreads();

    int d = tid & 127, q8 = tid >> 7;
    float acc = 0.f;
    for (int nl = q8; nl < PN; nl += 8) {
        float z = g_Z[(size_t)(g*PN + nl)*128 + d];
        float y0 = 0.f, y1 = 0.f;
#pragma unroll
        for (int c = 0; c < 4; c++) {
            y0 = fmaf(nm_s[c*256 + nl],       hcw[c*128 + d],       y0);
            y1 = fmaf(nm_s[(4 + c)*256 + nl], hcw[512 + c*128 + d], y1);
        }
        acc += 0.5f * (fmaxf(z + y0, 0.f) + fmaxf(z + y1, 0.f));
    }
    red[tid] = acc;
    __syncthreads();
    if (tid < 128) {
        float s = 0.f;
#pragma unroll
        for (int j = 0; j < 8; j++) s += red[tid + j*128];
        gs[tid] = s * (1.0f / PN);
    }
    __syncthreads();
    if (tid < 128) {
        float e = b_inter[tid];
        for (int k = 0; k < 128; k++) e = fmaf(gs[k], W_inter[k*128 + tid], e);
        emb[tid] = e;
    }
    __syncthreads();
    if (tid < OUTD) {
        float o = b_out[tid];
        for (int k = 0; k < 128; k++) o = fmaf(emb[k], W_out[k*OUTD + tid], o);
        out[g*OUTD + tid] = o;
    }
}

// ---------------------------------------------------------------------------
extern "C" void kernel_launch(void* const* d_in, const int* in_sizes, int n_in,
                              void* d_out, int out_size) {
    const float* x_feat    = (const float*)d_in[0];
    const float* edge_attr = (const float*)d_in[1];
    const float* W_atom    = (const float*)d_in[2];
    const float* b_atom    = (const float*)d_in[3];
    const float* W_score   = (const float*)d_in[4];
    const float* W_edge    = (const float*)d_in[5];
    const float* W_b2c     = (const float*)d_in[6];
    const float* W_bb      = (const float*)d_in[7];
    const float* W_bc      = (const float*)d_in[8];
    const float* W_cb      = (const float*)d_in[9];
    const float* W_cc      = (const float*)d_in[10];
    const float* W_sb      = (const float*)d_in[11];
    const float* W_sc      = (const float*)d_in[12];
    const float* W_inter   = (const float*)d_in[13];
    const float* b_inter   = (const float*)d_in[14];
    const float* W_out     = (const float*)d_in[15];
    const float* b_out     = (const float*)d_in[16];
    const int*   edge_index= (const int*)d_in[17];
    float* out = (float*)d_out;

    cudaFuncSetAttribute(mega1, cudaFuncAttributeMaxDynamicSharedMemorySize, 52000);
    cudaFuncSetAttribute(mega2, cudaFuncAttributeMaxDynamicSharedMemorySize, 95000);
    cudaFuncSetAttribute(graph_kernel, cudaFuncAttributeMaxDynamicSharedMemorySize, 145000);
    cudaFuncSetAttribute(final_kernel, cudaFuncAttributeMaxDynamicSharedMemorySize, 90000);

    const size_t smA = 128*17*8;   // packed u64 A tile = 17408

    // 1. fused weights + counter reset
    prep_big<<<277, 128>>>(W_atom, b_atom, W_b2c, W_sb, W_bb, W_edge, W_bc, W_score);
    // 2. h-GEMM (single wave)
    mega1<<<256, 256, 64*512 + smA>>>(x_feat);
    // 3. per-graph fused pass (nm, aggea/aggxf/deg, numh, bcxf, cx, ccraw)
    graph_kernel<<<NG, 1024, 143200>>>(x_feat, edge_attr, edge_index, W_edge);
    // 4. Z-GEMM + hcent partials in one launch (280 blocks, one wave)
    mega2<<<280, 256, (64+64+16)*512 + smA>>>(x_feat, W_cc, W_sc);
    // 5. fused hcw + Y + relu + mean + pool + heads
    final_kernel<<<NG, 1024, 88000>>>(W_cb, W_inter, b_inter, W_out, b_out, out);
}

// round 14
// speedup vs baseline: 1.6919x; 1.0080x over previous
#include <cuda_runtime.h>
#include <math.h>

#define NG   128
#define PN   256
#define EPG  1024
#define NN   (NG*PN)     // 32768
#define NE   (NG*EPG)    // 131072
#define DD   128
#define OUTD 10

// ---------------- device scratch ----------------
__device__ float g_h[NN*DD];
__device__ float g_nm[8*NN];              // [(r*4+c)*NN + n]
__device__ float g_aggxf[NN*64];
__device__ float g_deg[NN];
__device__ float g_aggea[NN*16];
__device__ float g_bcxf[2*NG*4*64];       // 1024 x 64:  sum_n nm * xf
__device__ float g_denr[2*NG*4];          // raw nm sums (no eps)
__device__ float g_cx[2*NG*4*DD];         // cent_x, 1024 x 128
__device__ float g_ccraw[2*NG*4*DD];      // Wgraw @ cent_x (unnormalized)
__device__ float g_hp[3*2*NG*4*DD];       // hcent partials (3 x 1024 x 128)
__device__ unsigned int g_maxbits;
__device__ float g_Z[NN*DD];
// fused weights
__device__ float g_Wab[64*128];           // Wa@W_b2c
__device__ float g_Wasb[64*128];          // Wa@W_sb
__device__ float g_Wawbb[64*128];         // Wa@W_bb
__device__ float g_WaWbc[64*128];         // Wa@W_bc
__device__ float g_W3[16*128];            // We@W_bb
__device__ float g_biash[128];            // ba@W_b2c
__device__ float g_biasz[128];            // ba@W_sb
__device__ float g_babb[128];             // ba@W_bb
__device__ float g_baWbc[128];            // ba@W_bc
__device__ float g_Was[64*8];             // Wa@W_score
__device__ float g_bs[8];                 // ba@W_score

// ---------------- packed f32x2 helpers ----------------
typedef unsigned long long u64t;
__device__ __forceinline__ u64t pk2(float lo, float hi) {
    u64t r; asm("mov.b64 %0, {%1,%2};" : "=l"(r) : "f"(lo), "f"(hi)); return r;
}
__device__ __forceinline__ void upk2(u64t v, float& lo, float& hi) {
    asm("mov.b64 {%0,%1}, %2;" : "=f"(lo), "=f"(hi) : "l"(v));
}
__device__ __forceinline__ void fma2(u64t& d, u64t a, u64t b) {
    asm("fma.rn.f32x2 %0, %1, %2, %0;" : "+l"(d) : "l"(a), "l"(b));
}

// ---------------------------------------------------------------------------
// GEMM pass: 128 rows x 128 cols per block, 256 threads.
// ---------------------------------------------------------------------------
template<bool SC>
__device__ __forceinline__ void mma_pass2(const float* __restrict__ A, int K,
                                          const float* __restrict__ Ws,
                                          u64t* As, int row0, int tid,
                                          int tr, int tc2, u64t acc[8][4],
                                          float ascale) {
    float4 pre[2];
#pragma unroll
    for (int it = 0; it < 2; it++) {
        int idx = tid + it*256; int lr = idx >> 2, lc = (idx & 3) * 4;
        pre[it] = *(const float4*)(A + (size_t)(row0 + lr)*K + lc);
    }
    for (int k0 = 0; k0 < K; k0 += 16) {
        __syncthreads();
#pragma unroll
        for (int it = 0; it < 2; it++) {
            int idx = tid + it*256; int lr = idx >> 2, lc = (idx & 3) * 4;
            float4 v = pre[it];
            if (SC) { v.x *= ascale; v.y *= ascale; v.z *= ascale; v.w *= ascale; }
            As[lr*17 + lc + 0] = pk2(v.x, v.x);
            As[lr*17 + lc + 1] = pk2(v.y, v.y);
            As[lr*17 + lc + 2] = pk2(v.z, v.z);
            As[lr*17 + lc + 3] = pk2(v.w, v.w);
        }
        __syncthreads();
        if (k0 + 16 < K) {
#pragma unroll
            for (int it = 0; it < 2; it++) {
                int idx = tid + it*256; int lr = idx >> 2, lc = (idx & 3) * 4;
                pre[it] = *(const float4*)(A + (size_t)(row0 + lr)*K + k0 + 16 + lc);
            }
        }
#pragma unroll
        for (int kk = 0; kk < 16; kk++) {
            const float* wrow = Ws + (k0 + kk)*128;
            u64t wv[4];
#pragma unroll
            for (int jp = 0; jp < 4; jp++)
                wv[jp] = *(const u64t*)(wrow + tc2 + 32*jp);
            u64t ap[8];
#pragma unroll
            for (int i = 0; i < 8; i++)
                ap[i] = As[(tr + 16*i)*17 + kk];
#pragma unroll
            for (int i = 0; i < 8; i++)
#pragma unroll
                for (int jp = 0; jp < 4; jp++) fma2(acc[i][jp], ap[i], wv[jp]);
        }
    }
}

__device__ __forceinline__ void acc_store(u64t acc[8][4], float* __restrict__ out,
                                          int row0, int tr, int tc2, int relu_flag) {
#pragma unroll
    for (int i = 0; i < 8; i++) {
        int row = row0 + tr + 16*i;
#pragma unroll
        for (int jp = 0; jp < 4; jp++) {
            int cb = tc2 + 32*jp;
            float lo, hi; upk2(acc[i][jp], lo, hi);
            if (relu_flag) { lo = fmaxf(lo, 0.f); hi = fmaxf(hi, 0.f); }
            out[(size_t)row*128 + cb]     = lo;
            out[(size_t)row*128 + cb + 1] = hi;
        }
    }
}

__device__ __forceinline__ void gemm_body(
        const float* __restrict__ A1, const float* __restrict__ W1, int K1,
        const float* __restrict__ A2, const float* __restrict__ W2, int K2,
        const float* __restrict__ A3, const float* __restrict__ W3, int K3,
        const float* __restrict__ bias,
        const float* __restrict__ rowscale,
        const float* __restrict__ rowvec,
        int relu_flag, float* __restrict__ out,
        int blk, float* sm) {
    float* Ws1 = sm;
    float* Ws2 = Ws1 + K1*128;
    float* Ws3 = Ws2 + K2*128;
    u64t*  As  = (u64t*)(Ws3 + K3*128);

    const int tid = threadIdx.x;
    const int tr = tid >> 4, tc2 = (tid & 15) * 2;
    const int row0 = blk * 128;

    for (int i = tid*4; i < K1*128; i += 1024) *(float4*)(Ws1+i) = *(const float4*)(W1+i);
    if (A2) for (int i = tid*4; i < K2*128; i += 1024) *(float4*)(Ws2+i) = *(const float4*)(W2+i);
    if (A3) for (int i = tid*4; i < K3*128; i += 1024) *(float4*)(Ws3+i) = *(const float4*)(W3+i);

    u64t acc[8][4];
#pragma unroll
    for (int i = 0; i < 8; i++)
#pragma unroll
        for (int j = 0; j < 4; j++) acc[i][j] = 0ull;

    mma_pass2<false>(A1, K1, Ws1, As, row0, tid, tr, tc2, acc, 1.f);
    if (A2) mma_pass2<false>(A2, K2, Ws2, As, row0, tid, tr, tc2, acc, 1.f);
    if (A3) mma_pass2<false>(A3, K3, Ws3, As, row0, tid, tr, tc2, acc, 1.f);

#pragma unroll
    for (int i = 0; i < 8; i++) {
        int row = row0 + tr + 16*i;
        float rs = rowscale ? rowscale[row] : 0.f;
#pragma unroll
        for (int jp = 0; jp < 4; jp++) {
            int cb = tc2 + 32*jp;
            float lo, hi; upk2(acc[i][jp], lo, hi);
            if (bias)   { lo += bias[cb];        hi += bias[cb+1]; }
            if (rowvec) { lo += rs * rowvec[cb]; hi += rs * rowvec[cb+1]; }
            if (relu_flag) { lo = fmaxf(lo, 0.f); hi = fmaxf(hi, 0.f); }
            out[(size_t)row*128 + cb]     = lo;
            out[(size_t)row*128 + cb + 1] = hi;
        }
    }
}

// ---------------------------------------------------------------------------
// MEGA1: pure h-GEMM, 256 blocks (single wave).
// ---------------------------------------------------------------------------
__global__ void __launch_bounds__(256, 2)
mega1(const float* __restrict__ x_feat) {
    extern __shared__ float sm[];
    gemm_body(x_feat, g_Wab, 64, nullptr, nullptr, 0, nullptr, nullptr, 0,
              g_biash, nullptr, nullptr, 1, g_h, blockIdx.x, sm);
}

// ---------------------------------------------------------------------------
// MEGA2: blocks 0-255 Z-GEMM (K=144);
// blocks 256-279: hcent partial GEMMs (hb = t&7, p = t>>3):
//   p0: bcxf(K=64)@WaWbc + denr*baWbc ; p1: (ccraw/max)@Wcc ; p2: cx@Wsc.
// ---------------------------------------------------------------------------
__global__ void __launch_bounds__(256, 2)
mega2(const float* __restrict__ x_feat,
      const float* __restrict__ Wcc_, const float* __restrict__ Wsc) {
    extern __shared__ float sm[];
    int b = blockIdx.x;
    if (b < 256) {
        gemm_body(g_aggxf, g_Wawbb, 64, x_feat, g_Wasb, 64, g_aggea, g_W3, 16,
                  g_biasz, g_deg, g_babb, 0, g_Z, b, sm);
        return;
    }
    const int t = b - 256;                 // 0..23
    const int hb = t & 7, p = t >> 3;
    const int tid = threadIdx.x;
    const int tr = tid >> 4, tc2 = (tid & 15) * 2;

    if (p == 0) {
        gemm_body(g_bcxf, g_WaWbc, 64, nullptr, nullptr, 0, nullptr, nullptr, 0,
                  nullptr, g_denr, g_baWbc, 0, g_hp, hb, sm);
    } else {
        float* Ws = sm;
        u64t*  As = (u64t*)(sm + 128*128);
        const int row0 = hb * 128;
        const float* Wsel = (p == 1) ? Wcc_ : Wsc;
        const float* Asel = (p == 1) ? g_ccraw : g_cx;
        const float ascale = (p == 1)
            ? 1.f / (__uint_as_float(g_maxbits) + 1e-9f) : 1.f;
        for (int i = tid*4; i < 128*128; i += 1024)
            *(float4*)(Ws+i) = *(const float4*)(Wsel+i);
        u64t acc[8][4];
#pragma unroll
        for (int i = 0; i < 8; i++)
#pragma unroll
            for (int j = 0; j < 4; j++) acc[i][j] = 0ull;
        mma_pass2<true>(Asel, 128, Ws, As, row0, tid, tr, tc2, acc, ascale);
        acc_store(acc, g_hp + (size_t)p*131072, row0, tr, tc2, 0);
    }
}

// ---------------------------------------------------------------------------
// Parallel weight precompute + counters reset.  grid = 277 x 128.
// ---------------------------------------------------------------------------
__global__ void prep_big(const float* __restrict__ Wa, const float* __restrict__ ba,
                         const float* __restrict__ Wb2c, const float* __restrict__ Wsb,
                         const float* __restrict__ Wbb, const float* __restrict__ We,
                         const float* __restrict__ Wbc, const float* __restrict__ Wscore) {
    int b = blockIdx.x, d = threadIdx.x;
    if (b < 64) {
        float a = 0.f;
        for (int k = 0; k < 128; k++) a = fmaf(Wa[b*128+k], Wb2c[k*128+d], a);
        g_Wab[b*128+d] = a;
    } else if (b < 128) {
        int f = b - 64; float a = 0.f;
        for (int k = 0; k < 128; k++) a = fmaf(Wa[f*128+k], Wsb[k*128+d], a);
        g_Wasb[f*128+d] = a;
    } else if (b < 144) {
        int q = b - 128; float a = 0.f;
        for (int k = 0; k < 128; k++) a = fmaf(We[q*128+k], Wbb[k*128+d], a);
        g_W3[q*128+d] = a;
    } else if (b < 208) {
        int f = b - 144; float a = 0.f;
        for (int k = 0; k < 128; k++) a = fmaf(Wa[f*128+k], Wbb[k*128+d], a);
        g_Wawbb[f*128+d] = a;
    } else if (b < 272) {
        int f = b - 208; float a = 0.f;
        for (int k = 0; k < 128; k++) a = fmaf(Wa[f*128+k], Wbc[k*128+d], a);
        g_WaWbc[f*128+d] = a;
    } else if (b == 272) {
        float a = 0.f;
        for (int k = 0; k < 128; k++) a = fmaf(ba[k], Wb2c[k*128+d], a);
        g_biash[d] = a;
    } else if (b == 273) {
        float a = 0.f;
        for (int k = 0; k < 128; k++) a = fmaf(ba[k], Wsb[k*128+d], a);
        g_biasz[d] = a;
    } else if (b == 274) {
        float a = 0.f;
        for (int k = 0; k < 128; k++) a = fmaf(ba[k], Wbb[k*128+d], a);
        g_babb[d] = a;
        if (d == 0) g_maxbits = 0u;
    } else if (b == 275) {
        float a = 0.f;
        for (int k = 0; k < 128; k++) a = fmaf(ba[k], Wbc[k*128+d], a);
        g_baWbc[d] = a;
    } else {
        for (int o = d; o < 520; o += 128) {
            int r = o >> 3, q = o & 7;
            const float* L = (r < 64) ? (Wa + r*128) : ba;
            float a = 0.f;
            for (int k = 0; k < 128; k++) a = fmaf(L[k], Wscore[k*8+q], a);
            if (r < 64) g_Was[r*8+q] = a; else g_bs[q] = a;
        }
    }
}

// ---------------------------------------------------------------------------
// Per-graph fused kernel.  1 block / graph, 1024 threads.
// Atomic-free reductions: src-CSR gather for srcw; partial-buffer reductions
// for bcxf and numh (in the reused ea_sm region).
// ---------------------------------------------------------------------------
__global__ void __launch_bounds__(1024)
graph_kernel(const float* __restrict__ xf,
             const float* __restrict__ edge_attr,
             const int* __restrict__ ei,
             const float* __restrict__ Wedge) {
    extern __shared__ float smf[];
    float* nm_sm    = smf;               // 2048
    float* srcw     = nm_sm + 2048;      // 2048
    float* ea_sm    = srcw + 2048;       // 16384 (xf stage -> edges -> partials -> cx)
    float* wnum_c   = ea_sm + 16384;     // 8192  (scores -> wnum -> We)
    float* numh_sm  = wnum_c + 8192;     // 1024
    float* red_sm   = numh_sm + 1024;    // 1024
    float* numea_sm = red_sm + 1024;     // 128
    float* was_sm   = numea_sm + 128;    // 520
    float* w_sm     = was_sm + 520;      // 24
    float* den_sm   = w_sm + 24;         // 8
    float* denr_sm  = den_sm + 8;        // 8
    int* sl    = (int*)(denr_sm + 8);    // 1024
    int* dl    = sl + 1024;              // 1024
    int* deg   = dl + 1024;              // 256
    int* off   = deg + 256;              // 257
    int* cur   = off + 257;              // 256
    int* csr   = cur + 256;              // 1024
    int* deg_s = csr + 1024;             // 256
    int* off_s = deg_s + 256;            // 257
    int* cur_s = off_s + 257;            // 256
    int* csr_s = cur_s + 256;            // 1024

    float* cx_sm = ea_sm;                // alias
    float* We_sm = wnum_c;               // alias

    const int g = blockIdx.x;
    const int tid = threadIdx.x;
    const int gb = g * PN;
    const int ge = g * EPG;

    // ---- nm phase: stage xf tile, scores, softmax ----
    for (int i = tid*4; i < PN*64; i += 4096)
        *(float4*)(ea_sm + i) = *(const float4*)(xf + (size_t)gb*64 + i);
    for (int i = tid; i < 512; i += 1024) was_sm[i] = g_Was[i];
    if (tid < 8) was_sm[512 + tid] = g_bs[tid];
    if (tid < PN) { deg[tid] = 0; deg_s[tid] = 0; }
    if (tid < 20) w_sm[tid] = 0.f;
    __syncthreads();
    {
        int node = tid >> 2, q = tid & 3;
        float s0 = was_sm[512 + q], s1 = was_sm[512 + q + 4];
        const float* xrow = ea_sm + node*64;
        for (int k = 0; k < 64; k++) {
            float a = xrow[k];
            s0 = fmaf(a, was_sm[k*8 + q], s0);
            s1 = fmaf(a, was_sm[k*8 + q + 4], s1);
        }
        wnum_c[node*8 + q]     = s0;
        wnum_c[node*8 + q + 4] = s1;
    }
    __syncthreads();
    if (tid < 512) {
        int node = tid >> 1, r = tid & 1;
        float v[4];
#pragma unroll
        for (int c = 0; c < 4; c++) v[c] = wnum_c[node*8 + c*2 + r];
        float m = fmaxf(fmaxf(v[0], v[1]), fmaxf(v[2], v[3]));
        float e[4], sum = 0.f;
#pragma unroll
        for (int c = 0; c < 4; c++) { e[c] = expf(v[c] - m); sum += e[c]; }
        float inv = 1.f / sum;
#pragma unroll
        for (int c = 0; c < 4; c++) {
            float nv = e[c] * inv;
            nm_sm[(r*4 + c)*256 + node] = nv;
            g_nm[(size_t)(r*4 + c)*NN + gb + node] = nv;
        }
    }
    __syncthreads();

    // ---- edge pass: one edge per thread (deg atomics only) ----
    float wp[20];
    {
        const int e = tid;
        int s = ei[ge + e] - gb;
        int d = ei[NE + ge + e] - gb;
        sl[e] = s; dl[e] = d;
        atomicAdd(&deg[d], 1);
        atomicAdd(&deg_s[s], 1);
        const float4* earow = (const float4*)(edge_attr + (size_t)(ge + e)*16);
        float4 e0 = earow[0], e1 = earow[1], e2 = earow[2], e3 = earow[3];

        float ns[8], nd[8];
#pragma unroll
        for (int rc = 0; rc < 8; rc++) {
            ns[rc] = nm_sm[rc*256 + s];
            nd[rc] = nm_sm[rc*256 + d];
        }
        __syncthreads();   // staged xf reads done; safe to overwrite ea_sm
        float4* eadst = (float4*)(ea_sm + e*16);
        eadst[0] = e0; eadst[1] = e1; eadst[2] = e2; eadst[3] = e3;
#pragma unroll
        for (int rc = 0; rc < 8; rc++)
            wnum_c[e*8 + rc] = nd[rc]*nd[rc]*ns[rc];
#pragma unroll
        for (int r = 0; r < 2; r++) {
            int b = r*4, w0 = r*10;
            wp[w0+0] = ns[b+0]*nd[b+1];
            wp[w0+1] = ns[b+0]*nd[b+2];
            wp[w0+2] = ns[b+0]*nd[b+3];
            wp[w0+3] = ns[b+1]*nd[b+2];
            wp[w0+4] = ns[b+1]*nd[b+3];
            wp[w0+5] = ns[b+2]*nd[b+3];
#pragma unroll
            for (int c = 0; c < 4; c++) wp[w0+6+c] = ns[b+c]*nd[b+c];
        }
    }
#pragma unroll
    for (int p = 0; p < 20; p++)
        for (int o = 16; o > 0; o >>= 1)
            wp[p] += __shfl_down_sync(0xffffffffu, wp[p], o);
    if ((tid & 31) == 0)
#pragma unroll
        for (int p = 0; p < 20; p++) atomicAdd(&w_sm[p], wp[p]);
    __syncthreads();

    // ---- numea partials (all threads) ----
    {
        const int eh = tid >> 7, rcb = (tid >> 4) & 7, qb = tid & 15;
        float nacc = 0.f;
        for (int el = eh*128; el < eh*128 + 128; el++)
            nacc = fmaf(wnum_c[el*8 + rcb], ea_sm[el*16 + qb], nacc);
        red_sm[tid] = nacc;
    }
    __syncthreads();
    if (tid < 256) {
        int rc = tid >> 5, lane = tid & 31;
        float s = 0.f;
        for (int n = lane; n < PN; n += 32) s += nm_sm[rc*256 + n];
        for (int o = 16; o > 0; o >>= 1) s += __shfl_down_sync(0xffffffffu, s, o);
        if (lane == 0) { denr_sm[rc] = s; den_sm[rc] = s + 1e-6f; }
    }
    if (tid >= 512 && tid < 640) {
        int t = tid - 512;
        float v = 0.f;
#pragma unroll
        for (int j = 0; j < 8; j++) v += red_sm[t + j*128];
        numea_sm[t] = v;
    }

    // ---- dual CSR scans: warp0 = dst, warp1 = src ----
    if (tid < 64) {
        int lane = tid & 31;
        int* dga = (tid < 32) ? deg : deg_s;
        int* ofa = (tid < 32) ? off : off_s;
        int run = 0;
        for (int seg = 0; seg < 8; seg++) {
            int dv = dga[seg*32 + lane];
            int v = dv;
#pragma unroll
            for (int o = 1; o < 32; o <<= 1) {
                int t = __shfl_up_sync(0xffffffffu, v, o);
                if (lane >= o) v += t;
            }
            ofa[seg*32 + lane] = run + v - dv;
            run += __shfl_sync(0xffffffffu, v, 31);
        }
        if (lane == 31) ofa[PN] = run;
    }
    __syncthreads();
    if (tid < PN) { cur[tid] = off[tid]; cur_s[tid] = off_s[tid]; }
    __syncthreads();
    {
        int pos = atomicAdd(&cur[dl[tid]], 1);
        csr[pos] = tid;
        int pos2 = atomicAdd(&cur_s[sl[tid]], 1);
        csr_s[pos2] = tid;
    }
    __syncthreads();

    if (tid < PN) g_deg[gb + tid] = (float)deg[tid];

    // srcw via src-CSR gather: task = (s, rc)
    for (int i = tid; i < PN*8; i += 1024) {
        int s = i >> 3, rc = i & 7;
        float a = 0.f;
        int e0 = off_s[s], e1 = off_s[s + 1];
        for (int ii = e0; ii < e1; ii++)
            a += wnum_c[csr_s[ii]*8 + rc];
        srcw[rc*256 + s] = a;
    }

    // aggea via dst-CSR
    for (int i = tid; i < PN*16; i += 1024) {
        int nl = i >> 4, q = i & 15;
        float a = 0.f;
        int e0 = off[nl], e1 = off[nl + 1];
        for (int ii = e0; ii < e1; ii++)
            a += ea_sm[csr[ii]*16 + q];
        g_aggea[(size_t)(gb + nl)*16 + q] = a;
    }
    __syncthreads();   // ea_sm free from here

    // ---- bcxf + aggxf: partial buffer in ea_sm (16 grp x 512) ----
    {
        const int d64 = tid & 63, grp = tid >> 6;
        float bl[8];
#pragma unroll
        for (int rc = 0; rc < 8; rc++) bl[rc] = 0.f;
        for (int nl = grp; nl < PN; nl += 16) {
            float xv = xf[(size_t)(gb + nl)*64 + d64];
#pragma unroll
            for (int rc = 0; rc < 8; rc++)
                bl[rc] = fmaf(nm_sm[rc*256 + nl], xv, bl[rc]);
            float a = 0.f;
            int e0 = off[nl], e1 = off[nl + 1];
            for (int ii = e0; ii < e1; ii++)
                a += xf[(size_t)(gb + sl[csr[ii]])*64 + d64];
            g_aggxf[(size_t)(gb + nl)*64 + d64] = a;
        }
#pragma unroll
        for (int rc = 0; rc < 8; rc++)
            ea_sm[grp*512 + rc*64 + d64] = bl[rc];
    }
    __syncthreads();
    if (tid < 512) {
        float s = 0.f;
#pragma unroll
        for (int j = 0; j < 16; j++) s += ea_sm[j*512 + tid];
        int rc = tid >> 6, q = tid & 63;
        int r = rc >> 2, ci = rc & 3;
        g_bcxf[((size_t)(r*NG + g)*4 + ci)*64 + q] = s;
    }
    if (tid < 8) {
        int r = tid >> 2, ci = tid & 3;
        g_denr[(size_t)(r*NG + g)*4 + ci] = denr_sm[tid];
    }
    __syncthreads();   // bcxf partial reads done; ea_sm free again

    // ---- numh: partial buffer in ea_sm (8 grp x 1024) ----
    {
        const int d = tid & 127, grp8 = tid >> 7;
        float numa[8];
#pragma unroll
        for (int rc = 0; rc < 8; rc++) numa[rc] = 0.f;
        for (int nl = grp8; nl < PN; nl += 8) {
            float hv = g_h[(size_t)(gb + nl)*128 + d];
#pragma unroll
            for (int rc = 0; rc < 8; rc++)
                numa[rc] = fmaf(nm_sm[rc*256 + nl] + srcw[rc*256 + nl], hv, numa[rc]);
        }
#pragma unroll
        for (int rc = 0; rc < 8; rc++)
            ea_sm[grp8*1024 + rc*128 + d] = numa[rc];
    }
    __syncthreads();
    {
        float s = 0.f;
#pragma unroll
        for (int j = 0; j < 8; j++) s += ea_sm[j*1024 + tid];
        numh_sm[tid] = s;
    }
    __syncthreads();   // numh partial reads done; ea_sm (cx_sm) free

    // ---- cx / ccraw phase (1024 threads = 8 rc x 128 d) ----
    {
        const int rc = tid >> 7, dd = tid & 127;
        const int r = rc >> 2, ci = rc & 3;
        for (int i = tid; i < 2048; i += 1024) We_sm[i] = Wedge[i];
        __syncthreads();
        float v = numh_sm[rc*128 + dd];
#pragma unroll
        for (int q = 0; q < 16; q++)
            v = fmaf(numea_sm[rc*16 + q], We_sm[q*128 + dd], v);
        v /= den_sm[rc];
        cx_sm[rc*128 + dd] = v;
        g_cx[((size_t)(r*NG + g)*4 + ci)*128 + dd] = v;
        __syncthreads();
        const int pidx[4][4] = { {6,0,1,2}, {0,7,3,4}, {1,3,8,5}, {2,4,5,9} };
        float a = 0.f;
#pragma unroll
        for (int j = 0; j < 4; j++) {
            float w = w_sm[r*10 + pidx[ci][j]];
            if (ci == j) w *= 0.5f;
            a = fmaf(w, cx_sm[(r*4 + j)*128 + dd], a);
        }
        g_ccraw[((size_t)(r*NG + g)*4 + ci)*128 + dd] = a;
    }

    if (tid < 32) {
        const int pidx[4][4] = { {6,0,1,2}, {0,7,3,4}, {1,3,8,5}, {2,4,5,9} };
        int r = tid >> 4, idx = tid & 15;
        int i = idx >> 2, j = idx & 3;
        float v = w_sm[r*10 + pidx[i][j]];
        if (i == j) v *= 0.5f;
        float m = v;
        for (int o = 16; o > 0; o >>= 1)
            m = fmaxf(m, __shfl_down_sync(0xffffffffu, m, o));
        if (tid == 0) atomicMax(&g_maxbits, __float_as_uint(m));
    }
}

// ---------------------------------------------------------------------------
// Final fused: hcw = relu(hp0+hp1+hp2)@Wcb (in-block, per graph);
// node = mean_r relu(Z + Sum_c nm*hcw); pool; heads.  grid = NG, 1024 thr.
// ---------------------------------------------------------------------------
__global__ void __launch_bounds__(1024)
final_kernel(const float* __restrict__ Wcb,
             const float* __restrict__ W_inter,
             const float* __restrict__ b_inter,
             const float* __restrict__ W_out,
             const float* __restrict__ b_out,
             float* __restrict__ out) {
    extern __shared__ float sm[];
    float* Wcb_s = sm;             // 16384
    float* hc    = Wcb_s + 16384;  // 1024
    float* hcw   = hc + 1024;      // 1024
    float* nm_s  = hcw + 1024;     // 2048
    float* red   = nm_s + 2048;    // 1024
    float* gs    = red + 1024;     // 128
    float* emb   = gs + 128;       // 128

    int g = blockIdx.x, tid = threadIdx.x;

    for (int i = tid*4; i < 16384; i += 4096)
        *(float4*)(Wcb_s + i) = *(const float4*)(Wcb + i);
    {
        int rc = tid >> 7, k = tid & 127;
        int r = rc >> 2, c = rc & 3;
        size_t o = ((size_t)(r*NG + g)*4 + c)*128 + k;
        float v = g_hp[o] + g_hp[131072 + o] + g_hp[262144 + o];
        hc[tid] = fmaxf(v, 0.f);
    }
    for (int i = tid; i < 2048; i += 1024)
        nm_s[i] = g_nm[(size_t)(i >> 8)*NN + g*PN + (i & 255)];
    __syncthreads();

    {
        int rc = tid >> 7, d = tid & 127;
        float a = 0.f;
#pragma unroll 4
        for (int k = 0; k < 128; k++)
            a = fmaf(hc[rc*128 + k], Wcb_s[k*128 + d], a);
        hcw[tid] = a;
    }
    __syncthreads();

    int d = tid & 127, q8 = tid >> 7;
    float acc = 0.f;
#pragma unroll 8
    for (int nl = q8; nl < PN; nl += 8) {
        float z = g_Z[(size_t)(g*PN + nl)*128 + d];
        float y0 = 0.f, y1 = 0.f;
#pragma unroll
        for (int c = 0; c < 4; c++) {
            y0 = fmaf(nm_s[c*256 + nl],       hcw[c*128 + d],       y0);
            y1 = fmaf(nm_s[(4 + c)*256 + nl], hcw[512 + c*128 + d], y1);
        }
        acc += 0.5f * (fmaxf(z + y0, 0.f) + fmaxf(z + y1, 0.f));
    }
    red[tid] = acc;
    __syncthreads();
    if (tid < 128) {
        float s = 0.f;
#pragma unroll
        for (int j = 0; j < 8; j++) s += red[tid + j*128];
        gs[tid] = s * (1.0f / PN);
    }
    __syncthreads();
    if (tid < 128) {
        float e = b_inter[tid];
        for (int k = 0; k < 128; k++) e = fmaf(gs[k], W_inter[k*128 + tid], e);
        emb[tid] = e;
    }
    __syncthreads();
    if (tid < OUTD) {
        float o = b_out[tid];
        for (int k = 0; k < 128; k++) o = fmaf(emb[k], W_out[k*OUTD + tid], o);
        out[g*OUTD + tid] = o;
    }
}

// ---------------------------------------------------------------------------
extern "C" void kernel_launch(void* const* d_in, const int* in_sizes, int n_in,
                              void* d_out, int out_size) {
    const float* x_feat    = (const float*)d_in[0];
    const float* edge_attr = (const float*)d_in[1];
    const float* W_atom    = (const float*)d_in[2];
    const float* b_atom    = (const float*)d_in[3];
    const float* W_score   = (const float*)d_in[4];
    const float* W_edge    = (const float*)d_in[5];
    const float* W_b2c     = (const float*)d_in[6];
    const float* W_bb      = (const float*)d_in[7];
    const float* W_bc      = (const float*)d_in[8];
    const float* W_cb      = (const float*)d_in[9];
    const float* W_cc      = (const float*)d_in[10];
    const float* W_sb      = (const float*)d_in[11];
    const float* W_sc      = (const float*)d_in[12];
    const float* W_inter   = (const float*)d_in[13];
    const float* b_inter   = (const float*)d_in[14];
    const float* W_out     = (const float*)d_in[15];
    const float* b_out     = (const float*)d_in[16];
    const int*   edge_index= (const int*)d_in[17];
    float* out = (float*)d_out;

    cudaFuncSetAttribute(mega1, cudaFuncAttributeMaxDynamicSharedMemorySize, 52000);
    cudaFuncSetAttribute(mega2, cudaFuncAttributeMaxDynamicSharedMemorySize, 95000);
    cudaFuncSetAttribute(graph_kernel, cudaFuncAttributeMaxDynamicSharedMemorySize, 152000);
    cudaFuncSetAttribute(final_kernel, cudaFuncAttributeMaxDynamicSharedMemorySize, 90000);

    const size_t smA = 128*17*8;   // packed u64 A tile = 17408

    // 1. fused weights + counter reset
    prep_big<<<277, 128>>>(W_atom, b_atom, W_b2c, W_sb, W_bb, W_edge, W_bc, W_score);
    // 2. h-GEMM (single wave)
    mega1<<<256, 256, 64*512 + smA>>>(x_feat);
    // 3. per-graph fused pass (nm, CSRs, srcw, aggea/aggxf, bcxf, numh, cx, ccraw)
    graph_kernel<<<NG, 1024, 148200>>>(x_feat, edge_attr, edge_index, W_edge);
    // 4. Z-GEMM + hcent partials in one launch (280 blocks, one wave)
    mega2<<<280, 256, (64+64+16)*512 + smA>>>(x_feat, W_cc, W_sc);
    // 5. fused hcw + Y + relu + mean + pool + heads
    final_kernel<<<NG, 1024, 88000>>>(W_cb, W_inter, b_inter, W_out, b_out, out);
}